// round 15
// baseline (speedup 1.0000x reference)
#include <cuda_runtime.h>
#include <cuda_fp16.h>
#include <math.h>
#include <stdint.h>

#define BSZ   4096
#define SEQ   36
#define DM    128
#define DFFN  512
#define NLAYER 8
#define FLATD (SEQ*DM)      // 4608
#define FC1N  13824

// ---------------- static scratch ----------------
__device__ float g_h  [(size_t)BSZ*FLATD];
__device__ float g_s  [(size_t)BSZ*FLATD];
__device__ float g_t512[(size_t)BSZ*SEQ*DFFN];   // QKV block [BL][384] / FFN scratch / z2
__device__ float g_z1 [(size_t)BSZ*FC1N];
__device__ float g_wvo[(size_t)NLAYER*DM*DM];    // Wv @ Wo per layer (fp32)
__device__ float g_bvo[(size_t)NLAYER*DM];
// fp16 hi/lo transposed weight planes [N][K]
__device__ __half g_w1h[(size_t)FC1N*FLATD];
__device__ __half g_w1l[(size_t)FC1N*FLATD];
__device__ __half g_w2h[(size_t)FLATD*FC1N];
__device__ __half g_w2l[(size_t)FLATD*FC1N];
// encoder weight planes: q,k,vo per layer [384][128] packed; conv1 [512][128]; conv2 [128][512]
__device__ __half g_eqh[(size_t)NLAYER*3*DM*DM];
__device__ __half g_eql[(size_t)NLAYER*3*DM*DM];
__device__ __half g_c1h[(size_t)NLAYER*DFFN*DM];
__device__ __half g_c1l[(size_t)NLAYER*DFFN*DM];
__device__ __half g_c2h[(size_t)NLAYER*DM*DFFN];
__device__ __half g_c2l[(size_t)NLAYER*DM*DFFN];
__device__ float  g_bqkv[(size_t)NLAYER*384];

// ============================================================================
// fp32 SGEMM — embed only (K=36)
// ============================================================================
#define BM 128
#define BN 128
#define BK 16
#define PADA 17

template<int DO_GELU, int HAS_BIAS>
__global__ __launch_bounds__(256, 2)
void sgemm_kernel(const float* __restrict__ A, const float* __restrict__ W,
                  const float* __restrict__ bias, float* __restrict__ C,
                  int M, int N, int K)
{
    __shared__ float As[BM][PADA];
    __shared__ float Ws[BK][BN];

    const int tid = threadIdx.x;
    const int tx  = tid & 15;
    const int ty  = tid >> 4;
    const size_t bm = blockIdx.y;
    const size_t bn = blockIdx.x;

    const float* Ab = A + bm * BM * (size_t)K;
    const float* Wb = W + bn * BN;

    float acc[8][8];
    #pragma unroll
    for (int i = 0; i < 8; i++)
        #pragma unroll
        for (int j = 0; j < 8; j++) acc[i][j] = 0.f;

    const int ka = tid & 15;
    const int ma = tid >> 4;
    const int nw = tid & 127;
    const int kw = tid >> 7;

    for (int k0 = 0; k0 < K; k0 += BK) {
        const bool kaok = (k0 + ka) < K;
        #pragma unroll
        for (int i = 0; i < 8; i++) {
            int m = ma + i * 16;
            float val = 0.f;
            if (kaok) val = Ab[(size_t)m * K + k0 + ka];
            As[m][ka] = val;
        }
        #pragma unroll
        for (int i = 0; i < 8; i++) {
            int kk = kw + i * 2;
            float val = 0.f;
            if (k0 + kk < K) val = Wb[(size_t)(k0 + kk) * N + nw];
            Ws[kk][nw] = val;
        }
        __syncthreads();

        #pragma unroll
        for (int kk = 0; kk < BK; kk++) {
            float ar[8];
            #pragma unroll
            for (int i = 0; i < 8; i++) ar[i] = As[ty * 8 + i][kk];
            float4 b0 = *(const float4*)&Ws[kk][tx * 8];
            float4 b1 = *(const float4*)&Ws[kk][tx * 8 + 4];
            float br[8] = {b0.x, b0.y, b0.z, b0.w, b1.x, b1.y, b1.z, b1.w};
            #pragma unroll
            for (int i = 0; i < 8; i++)
                #pragma unroll
                for (int j = 0; j < 8; j++)
                    acc[i][j] += ar[i] * br[j];
        }
        __syncthreads();
    }

    float bv[8];
    #pragma unroll
    for (int j = 0; j < 8; j++) bv[j] = 0.f;
    if (HAS_BIAS) {
        #pragma unroll
        for (int j = 0; j < 8; j++) bv[j] = bias[bn * BN + tx * 8 + j];
    }

    #pragma unroll
    for (int i = 0; i < 8; i++) {
        size_t row = bm * BM + ty * 8 + i;
        float* Cp = C + row * (size_t)N + bn * BN + tx * 8;
        float o[8];
        #pragma unroll
        for (int j = 0; j < 8; j++) {
            float vv = acc[i][j] + bv[j];
            if (DO_GELU) vv = 0.5f * vv * (1.f + erff(vv * 0.70710678118654752f));
            o[j] = vv;
        }
        *(float4*)Cp       = make_float4(o[0], o[1], o[2], o[3]);
        *(float4*)(Cp + 4) = make_float4(o[4], o[5], o[6], o[7]);
    }
}

// ============================================================================
// batched Wvo = Wv @ Wo (fp32 exact, one 128x128x128 per layer, same math
// as sgemm_kernel's 128x128 block: bit-identical)
// ============================================================================
__global__ __launch_bounds__(256, 2)
void wvo_gemm_kernel(const float* __restrict__ Wv, const float* __restrict__ Wo,
                     float* __restrict__ Cout)
{
    __shared__ float As[BM][PADA];
    __shared__ float Ws[BK][BN];

    const int tid = threadIdx.x;
    const int tx  = tid & 15;
    const int ty  = tid >> 4;
    const size_t lay = blockIdx.x;
    const float* Ab = Wv + lay * DM * DM;
    const float* Wb = Wo + lay * DM * DM;
    float* C = Cout + lay * DM * DM;

    float acc[8][8];
    #pragma unroll
    for (int i = 0; i < 8; i++)
        #pragma unroll
        for (int j = 0; j < 8; j++) acc[i][j] = 0.f;

    const int ka = tid & 15;
    const int ma = tid >> 4;
    const int nw = tid & 127;
    const int kw = tid >> 7;

    for (int k0 = 0; k0 < DM; k0 += BK) {
        #pragma unroll
        for (int i = 0; i < 8; i++) {
            int m = ma + i * 16;
            As[m][ka] = Ab[(size_t)m * DM + k0 + ka];
        }
        #pragma unroll
        for (int i = 0; i < 8; i++) {
            int kk = kw + i * 2;
            Ws[kk][nw] = Wb[(size_t)(k0 + kk) * DM + nw];
        }
        __syncthreads();

        #pragma unroll
        for (int kk = 0; kk < BK; kk++) {
            float ar[8];
            #pragma unroll
            for (int i = 0; i < 8; i++) ar[i] = As[ty * 8 + i][kk];
            float4 b0 = *(const float4*)&Ws[kk][tx * 8];
            float4 b1 = *(const float4*)&Ws[kk][tx * 8 + 4];
            float br[8] = {b0.x, b0.y, b0.z, b0.w, b1.x, b1.y, b1.z, b1.w};
            #pragma unroll
            for (int i = 0; i < 8; i++)
                #pragma unroll
                for (int j = 0; j < 8; j++)
                    acc[i][j] += ar[i] * br[j];
        }
        __syncthreads();
    }

    #pragma unroll
    for (int i = 0; i < 8; i++) {
        size_t row = ty * 8 + i;
        float* Cp = C + row * DM + tx * 8;
        *(float4*)Cp       = make_float4(acc[i][0], acc[i][1], acc[i][2], acc[i][3]);
        *(float4*)(Cp + 4) = make_float4(acc[i][4], acc[i][5], acc[i][6], acc[i][7]);
    }
}

// ============================================================================
// prep kernels (layer-batched via blockIdx.z)
// ============================================================================
__global__ __launch_bounds__(256)
void tsplit_kernel(const float* __restrict__ src, __half* __restrict__ dh,
                   __half* __restrict__ dl, int K, int N,
                   size_t srcStride, size_t dstStride)
{
    __shared__ float t[32][33];
    const size_t z = blockIdx.z;
    const float* s = src + z * srcStride;
    __half* dhh = dh + z * dstStride;
    __half* dll = dl + z * dstStride;
    const int n0 = blockIdx.x * 32, k0 = blockIdx.y * 32;
    const int tx = threadIdx.x, ty = threadIdx.y;   // 32 x 8
    #pragma unroll
    for (int j = 0; j < 32; j += 8)
        t[ty + j][tx] = s[(size_t)(k0 + ty + j) * N + n0 + tx];
    __syncthreads();
    #pragma unroll
    for (int j = 0; j < 32; j += 8) {
        float v = t[tx][ty + j];
        __half h = __float2half_rn(v);
        const size_t o = (size_t)(n0 + ty + j) * K + k0 + tx;
        dhh[o] = h;
        dll[o] = __float2half_rn(v - __half2float(h));
    }
}

__global__ __launch_bounds__(128)
void bvo_kernel(const float* __restrict__ bv, const float* __restrict__ Wo,
                const float* __restrict__ bo, float* __restrict__ bvo)
{
    const int i = blockIdx.x;
    const int j = threadIdx.x;
    const float* bvp = bv + i * DM;
    const float* wop = Wo + (size_t)i * DM * DM + j;
    float s = 0.f;
    #pragma unroll 8
    for (int k = 0; k < DM; k++) s += bvp[k] * wop[(size_t)k * DM];
    bvo[i * DM + j] = s + bo[i * DM + j];
}

__global__ __launch_bounds__(384)
void packb_kernel(const float* __restrict__ bq, const float* __restrict__ bk,
                  const float* __restrict__ bvo, float* __restrict__ dst)
{
    const int i = blockIdx.x;
    const int t = threadIdx.x;
    float v = (t < 128) ? bq[i * 128 + t]
            : (t < 256) ? bk[i * 128 + t - 128]
                        : bvo[i * 128 + t - 256];
    dst[i * 384 + t] = v;
}

// ============================================================================
// 3xFP16 tensor-core GEMM v4: M-tile 256, 512 threads (16 warps, 4Mx4N).
// Per-warp mainloop identical to v3 (bit-identical outputs).
// TWO_PASS=1 (head): drop Al*Bh pass -> fp16(A) x exact B.
// ============================================================================
#define USTR   20
#define APLANE (256*USTR)            // 5120 u32
#define BPLANE (128*USTR)            // 2560 u32
#define OFF_AL (APLANE)
#define OFF_BH (2*APLANE)
#define OFF_BL (2*APLANE + BPLANE)
#define STG_U  (2*APLANE + 2*BPLANE) // 15360 u32
#define HSM    (2*STG_U*4)           // 122880 bytes

__device__ __forceinline__ uint32_t packh(__half a, __half b) {
    __half2 t = __halves2half2(a, b);
    return *reinterpret_cast<uint32_t*>(&t);
}
__device__ __forceinline__ uint32_t smem_u32p(const void* p) {
    uint32_t a;
    asm("{ .reg .u64 t; cvta.to.shared.u64 t, %1; cvt.u32.u64 %0, t; }" : "=r"(a) : "l"(p));
    return a;
}
__device__ __forceinline__ void cp16(uint32_t dst, const void* src) {
    asm volatile("cp.async.cg.shared.global [%0], [%1], 16;" :: "r"(dst), "l"(src) : "memory");
}

#define LDSM4(R0, R1, R2, R3, ADDR)                                              \
    asm volatile("ldmatrix.sync.aligned.m8n8.x4.shared.b16 {%0,%1,%2,%3}, [%4];" \
        : "=r"(R0), "=r"(R1), "=r"(R2), "=r"(R3) : "r"(ADDR))

#define MMA_F16(ACC, A0, A1, A2, A3, B0, B1)                                    \
    asm volatile(                                                                \
        "mma.sync.aligned.m16n8k16.row.col.f32.f16.f16.f32 "                    \
        "{%0,%1,%2,%3}, {%4,%5,%6,%7}, {%8,%9}, {%0,%1,%2,%3};\n"               \
        : "+f"(ACC[0]), "+f"(ACC[1]), "+f"(ACC[2]), "+f"(ACC[3])                \
        : "r"(A0), "r"(A1), "r"(A2), "r"(A3), "r"(B0), "r"(B1))

template<int DO_GELU, int HAS_BIAS, int TWO_PASS>
__global__ __launch_bounds__(512, 1)
void hgemm3_kernel(const float* __restrict__ A, const __half* __restrict__ Wh,
                   const __half* __restrict__ Wl, const float* __restrict__ bias,
                   float* __restrict__ C, int M, int N, int K, int nbn)
{
    extern __shared__ uint32_t smem[];

    const int tid  = threadIdx.x;
    const int warp = tid >> 5;
    const int lane = tid & 31;
    const int wm = warp >> 2;      // 0..3 -> 64-row bands over 256
    const int wn = warp & 3;       // 0..3 -> 32-col bands over 128
    const int g  = lane >> 2;
    const int t4 = lane & 3;

    const int per = 8 * nbn;
    const int bm = (blockIdx.x / per) * 8 + (blockIdx.x % per) % 8;
    const int bn = (blockIdx.x % per) / 8;
    const size_t bm0 = (size_t)bm * 256;
    const int bn0 = bn * 128;

    // A loader: 512 threads, 2 per row (256 rows)
    const int arow = tid >> 1;
    const int ao0  = (tid & 1) * 8;          // u32 within row
    const float* ap = A + (bm0 + arow) * (size_t)K + ao0 * 2;

    // B loader: 4 threads per row (128 rows): sub 0/1 -> Bh kh 0/8; 2/3 -> Bl
    const int brow = tid >> 2;
    const int bsub = tid & 3;
    const int bkh  = (bsub & 1) * 8;         // u32 within row
    const __half* bp = ((bsub >> 1) ? Wl : Wh) + (size_t)(bn0 + brow) * K + bkh * 2;
    const uint32_t bplane = (bsub >> 1) ? OFF_BL : OFF_BH;

    const uint32_t smb = smem_u32p(smem);
    const int aoff = arow * USTR + ao0;
    const uint32_t bdst = (bplane + (uint32_t)(brow * USTR + bkh)) * 4;

    const int l15 = lane & 15;
    const uint32_t a_base = ((uint32_t)(wm * 64 + l15) * USTR + (lane >> 4) * 4) * 4;
    const int bl7 = (lane & 7) + ((lane >> 4) << 3);
    const uint32_t b_base = ((uint32_t)(wn * 32 + bl7) * USTR + ((lane >> 3) & 1) * 4) * 4;

    float acc[4][4][4];
    #pragma unroll
    for (int mi = 0; mi < 4; mi++)
        #pragma unroll
        for (int ni = 0; ni < 4; ni++)
            #pragma unroll
            for (int r = 0; r < 4; r++) acc[mi][ni][r] = 0.f;

    // ---- prologue: stage 0 ----
    {
        cp16(smb + bdst,      bp);
        cp16(smb + bdst + 16, bp + 8);
        asm volatile("cp.async.commit_group;" ::: "memory");

        float4 pa0 = *(const float4*)(ap);
        float4 pa1 = *(const float4*)(ap + 4);
        float4 pa2 = *(const float4*)(ap + 8);
        float4 pa3 = *(const float4*)(ap + 12);
        float fv[16] = {pa0.x, pa0.y, pa0.z, pa0.w, pa1.x, pa1.y, pa1.z, pa1.w,
                        pa2.x, pa2.y, pa2.z, pa2.w, pa3.x, pa3.y, pa3.z, pa3.w};
        uint32_t uh[8], ul[8];
        #pragma unroll
        for (int j = 0; j < 8; j++) {
            float a0 = fv[2 * j], a1 = fv[2 * j + 1];
            __half h0 = __float2half_rn(a0), h1 = __float2half_rn(a1);
            uh[j] = packh(h0, h1);
            if (!TWO_PASS)
                ul[j] = packh(__float2half_rn(a0 - __half2float(h0)),
                              __float2half_rn(a1 - __half2float(h1)));
        }
        *(uint4*)&smem[aoff]             = make_uint4(uh[0], uh[1], uh[2], uh[3]);
        *(uint4*)&smem[aoff + 4]         = make_uint4(uh[4], uh[5], uh[6], uh[7]);
        if (!TWO_PASS) {
            *(uint4*)&smem[OFF_AL + aoff]     = make_uint4(ul[0], ul[1], ul[2], ul[3]);
            *(uint4*)&smem[OFF_AL + aoff + 4] = make_uint4(ul[4], ul[5], ul[6], ul[7]);
        }
        asm volatile("cp.async.wait_group 0;" ::: "memory");
    }
    __syncthreads();

    float4 pa0, pa1, pa2, pa3;
    int it = 0;
    for (int k0 = 0; k0 < K; k0 += 32, it++) {
        const int cur = it & 1;
        const int nxt = cur ^ 1;
        const bool more = (k0 + 32) < K;

        if (more) {
            const int kn = k0 + 32;
            const uint32_t nb = smb + (uint32_t)nxt * STG_U * 4;
            cp16(nb + bdst,      bp + kn);
            cp16(nb + bdst + 16, bp + kn + 8);
            asm volatile("cp.async.commit_group;" ::: "memory");
            pa0 = *(const float4*)(ap + kn);
            pa1 = *(const float4*)(ap + kn + 4);
            pa2 = *(const float4*)(ap + kn + 8);
            pa3 = *(const float4*)(ap + kn + 12);
        }

        const uint32_t stb = smb + (uint32_t)cur * STG_U * 4;
        #pragma unroll
        for (int ks = 0; ks < 2; ks++) {
            const uint32_t kbb = ks * 32;
            uint32_t af[4][4], al_[4][4], bf[4][2], bt[4][2];
            #pragma unroll
            for (int mi = 0; mi < 4; mi++) {
                const uint32_t ao = stb + a_base + (uint32_t)(mi * 16 * USTR) * 4 + kbb;
                LDSM4(af[mi][0], af[mi][1], af[mi][2], af[mi][3], ao);
                if (!TWO_PASS)
                    LDSM4(al_[mi][0], al_[mi][1], al_[mi][2], al_[mi][3], ao + OFF_AL * 4);
            }
            {
                const uint32_t bo0 = stb + OFF_BH * 4 + b_base + kbb;
                const uint32_t bo1 = bo0 + (uint32_t)(16 * USTR) * 4;
                LDSM4(bf[0][0], bf[0][1], bf[1][0], bf[1][1], bo0);
                LDSM4(bf[2][0], bf[2][1], bf[3][0], bf[3][1], bo1);
                LDSM4(bt[0][0], bt[0][1], bt[1][0], bt[1][1], bo0 + BPLANE * 4);
                LDSM4(bt[2][0], bt[2][1], bt[3][0], bt[3][1], bo1 + BPLANE * 4);
            }
            // pass 1: Ah * Bh
            #pragma unroll
            for (int mi = 0; mi < 4; mi++)
                #pragma unroll
                for (int ni = 0; ni < 4; ni++)
                    MMA_F16(acc[mi][ni], af[mi][0], af[mi][1], af[mi][2], af[mi][3],
                            bf[ni][0], bf[ni][1]);
            // pass 2: Ah * Bl
            #pragma unroll
            for (int mi = 0; mi < 4; mi++)
                #pragma unroll
                for (int ni = 0; ni < 4; ni++)
                    MMA_F16(acc[mi][ni], af[mi][0], af[mi][1], af[mi][2], af[mi][3],
                            bt[ni][0], bt[ni][1]);
            // pass 3: Al * Bh (skipped for TWO_PASS)
            if (!TWO_PASS) {
                #pragma unroll
                for (int mi = 0; mi < 4; mi++)
                    #pragma unroll
                    for (int ni = 0; ni < 4; ni++)
                        MMA_F16(acc[mi][ni], al_[mi][0], al_[mi][1], al_[mi][2], al_[mi][3],
                                bf[ni][0], bf[ni][1]);
            }
        }

        if (more) {
            float fv[16] = {pa0.x, pa0.y, pa0.z, pa0.w, pa1.x, pa1.y, pa1.z, pa1.w,
                            pa2.x, pa2.y, pa2.z, pa2.w, pa3.x, pa3.y, pa3.z, pa3.w};
            uint32_t uh[8], ul[8];
            #pragma unroll
            for (int j = 0; j < 8; j++) {
                float a0 = fv[2 * j], a1 = fv[2 * j + 1];
                __half h0 = __float2half_rn(a0), h1 = __float2half_rn(a1);
                uh[j] = packh(h0, h1);
                if (!TWO_PASS)
                    ul[j] = packh(__float2half_rn(a0 - __half2float(h0)),
                                  __float2half_rn(a1 - __half2float(h1)));
            }
            uint32_t* sb = smem + nxt * STG_U;
            *(uint4*)&sb[aoff]             = make_uint4(uh[0], uh[1], uh[2], uh[3]);
            *(uint4*)&sb[aoff + 4]         = make_uint4(uh[4], uh[5], uh[6], uh[7]);
            if (!TWO_PASS) {
                *(uint4*)&sb[OFF_AL + aoff]     = make_uint4(ul[0], ul[1], ul[2], ul[3]);
                *(uint4*)&sb[OFF_AL + aoff + 4] = make_uint4(ul[4], ul[5], ul[6], ul[7]);
            }
            asm volatile("cp.async.wait_group 0;" ::: "memory");
        }
        __syncthreads();
    }

    // epilogue
    #pragma unroll
    for (int ni = 0; ni < 4; ni++) {
        const int col = bn0 + wn * 32 + ni * 8 + 2 * t4;
        float b0 = 0.f, b1 = 0.f;
        if (HAS_BIAS) { b0 = bias[col]; b1 = bias[col + 1]; }
        #pragma unroll
        for (int mi = 0; mi < 4; mi++) {
            #pragma unroll
            for (int hh = 0; hh < 2; hh++) {
                const size_t row = bm0 + wm * 64 + mi * 16 + g + hh * 8;
                float v0 = acc[mi][ni][2 * hh]     + b0;
                float v1 = acc[mi][ni][2 * hh + 1] + b1;
                if (DO_GELU) {
                    v0 = 0.5f * v0 * (1.f + erff(v0 * 0.70710678118654752f));
                    v1 = 0.5f * v1 * (1.f + erff(v1 * 0.70710678118654752f));
                }
                *(float2*)(C + row * (size_t)N + col) = make_float2(v0, v1);
            }
        }
    }
}

// ============================================================================
// AutoCorrelation + fused series_decomp residual (reads QKV [BL][384])
// ============================================================================
__global__ __launch_bounds__(128)
void autocorr_decomp_kernel(const float* __restrict__ QKV, float* __restrict__ H)
{
    const int b = blockIdx.x;
    const int c = threadIdx.x;
    const size_t qbase = (size_t)b * SEQ * 384 + c;
    const size_t obase = (size_t)b * FLATD + c;

    float qr[SEQ], kr[SEQ];
    #pragma unroll
    for (int t = 0; t < SEQ; t++) {
        qr[t] = QKV[qbase + (size_t)t * 384];
        kr[t] = QKV[qbase + (size_t)t * 384 + 128];
    }

    float acc[SEQ];
    #pragma unroll
    for (int tau = 0; tau < SEQ; tau++) {
        float s = 0.f;
        #pragma unroll
        for (int t = 0; t < SEQ; t++) s += qr[t] * kr[(t + SEQ - tau) % SEQ];
        acc[tau] = s;
    }

    const int lane = c & 31, wid = c >> 5;
    __shared__ float red[SEQ][4];
    #pragma unroll
    for (int tau = 0; tau < SEQ; tau++) {
        float s = acc[tau];
        s += __shfl_down_sync(0xffffffffu, s, 16);
        s += __shfl_down_sync(0xffffffffu, s, 8);
        s += __shfl_down_sync(0xffffffffu, s, 4);
        s += __shfl_down_sync(0xffffffffu, s, 2);
        s += __shfl_down_sync(0xffffffffu, s, 1);
        if (lane == 0) red[tau][wid] = s;
    }
    __syncthreads();

    __shared__ float corr[SEQ];
    if (c < SEQ) corr[c] = (red[c][0] + red[c][1] + red[c][2] + red[c][3]) * (1.f / 128.f);
    __syncthreads();

    __shared__ float wsm[3];
    __shared__ int   dsm[3];
    if (c == 0) {
        float tmp[SEQ];
        for (int t = 0; t < SEQ; t++) tmp[t] = corr[t];
        float wv[3]; int dv[3];
        for (int r = 0; r < 3; r++) {
            float best = tmp[0]; int bi = 0;
            for (int t = 1; t < SEQ; t++)
                if (tmp[t] > best) { best = tmp[t]; bi = t; }
            wv[r] = best; dv[r] = bi;
            tmp[bi] = -1e30f;
        }
        float m = wv[0];
        float e0 = expf(wv[0] - m), e1 = expf(wv[1] - m), e2 = expf(wv[2] - m);
        float inv = 1.f / (e0 + e1 + e2);
        wsm[0] = e0 * inv; wsm[1] = e1 * inv; wsm[2] = e2 * inv;
        dsm[0] = dv[0]; dsm[1] = dv[1]; dsm[2] = dv[2];
    }
    __syncthreads();

    const float w0 = wsm[0], w1 = wsm[1], w2 = wsm[2];
    const int   d0 = dsm[0], d1 = dsm[1], d2 = dsm[2];
    const float* vb = QKV + qbase + 256;

    float p[SEQ];
    #pragma unroll
    for (int t = 0; t < SEQ; t++) {
        int j0 = t + d0; if (j0 >= SEQ) j0 -= SEQ;
        int j1 = t + d1; if (j1 >= SEQ) j1 -= SEQ;
        int j2 = t + d2; if (j2 >= SEQ) j2 -= SEQ;
        float a = w0 * vb[(size_t)j0 * 384] + w1 * vb[(size_t)j1 * 384]
                + w2 * vb[(size_t)j2 * 384];
        p[t] = H[obase + (size_t)t * DM] + a;
    }

    float run = 12.f * p[0];
    #pragma unroll
    for (int j = 0; j <= 12; j++) run += p[j];
    #pragma unroll
    for (int t = 0; t < SEQ; t++) {
        H[obase + (size_t)t * DM] = p[t] - run * (1.f / 25.f);
        int jn = t + 13; if (jn > SEQ - 1) jn = SEQ - 1;
        int jo = t - 12; if (jo < 0) jo = 0;
        run += p[jn] - p[jo];
    }
}

// ---------------- series_decomp with fused residual add (FFN branch) ----------------
__global__ __launch_bounds__(128)
void decomp_add_kernel(const float* __restrict__ hin, const float* __restrict__ sin_,
                       float* __restrict__ hout)
{
    const int b = blockIdx.x;
    const int c = threadIdx.x;
    __shared__ float p[SEQ][DM];
    const size_t base = (size_t)b * FLATD + c;
    #pragma unroll
    for (int t = 0; t < SEQ; t++)
        p[t][c] = hin[base + t * DM] + sin_[base + t * DM];
    __syncthreads();

    float run = 12.f * p[0][c];
    #pragma unroll
    for (int j = 0; j <= 12; j++) run += p[j][c];
    #pragma unroll
    for (int t = 0; t < SEQ; t++) {
        hout[base + t * DM] = p[t][c] - run * (1.f / 25.f);
        int jn = t + 13; if (jn > SEQ - 1) jn = SEQ - 1;
        int jo = t - 12; if (jo < 0) jo = 0;
        run += p[jn][c] - p[jo][c];
    }
}

// ---------------- my_Layernorm ----------------
__global__ __launch_bounds__(128)
void ln_kernel(const float* __restrict__ hin, const float* __restrict__ lnw,
               const float* __restrict__ lnb, float* __restrict__ hout)
{
    const int b = blockIdx.x;
    const int c = threadIdx.x;
    const int lane = c & 31, wid = c >> 5;
    __shared__ float xs[SEQ][DM];
    __shared__ float r1[4], r2[4];
    const size_t base = (size_t)b * FLATD + c;
    #pragma unroll
    for (int t = 0; t < SEQ; t++) xs[t][c] = hin[base + t * DM];
    __syncthreads();

    const float gw = lnw[c], gb = lnb[c];
    for (int t = 0; t < SEQ; t++) {
        float val = xs[t][c];
        float s = val;
        s += __shfl_down_sync(0xffffffffu, s, 16);
        s += __shfl_down_sync(0xffffffffu, s, 8);
        s += __shfl_down_sync(0xffffffffu, s, 4);
        s += __shfl_down_sync(0xffffffffu, s, 2);
        s += __shfl_down_sync(0xffffffffu, s, 1);
        if (lane == 0) r1[wid] = s;
        __syncthreads();
        float mean = (r1[0] + r1[1] + r1[2] + r1[3]) * (1.f / 128.f);
        float d = val - mean;
        float sq = d * d;
        sq += __shfl_down_sync(0xffffffffu, sq, 16);
        sq += __shfl_down_sync(0xffffffffu, sq, 8);
        sq += __shfl_down_sync(0xffffffffu, sq, 4);
        sq += __shfl_down_sync(0xffffffffu, sq, 2);
        sq += __shfl_down_sync(0xffffffffu, sq, 1);
        if (lane == 0) r2[wid] = sq;
        __syncthreads();
        float var = (r2[0] + r2[1] + r2[2] + r2[3]) * (1.f / 128.f);
        xs[t][c] = d * (1.f / sqrtf(var + 1e-5f)) * gw + gb;
    }
    float cm = 0.f;
    #pragma unroll
    for (int t = 0; t < SEQ; t++) cm += xs[t][c];
    cm *= (1.f / 36.f);
    #pragma unroll
    for (int t = 0; t < SEQ; t++)
        hout[base + t * DM] = xs[t][c] - cm;
}

// ---------------- fc3 [4608 -> 2] + softmax ----------------
__global__ __launch_bounds__(256)
void fc3_softmax_kernel(const float* __restrict__ z, const float* __restrict__ w,
                        const float* __restrict__ bias, float* __restrict__ out)
{
    const int b = blockIdx.x;
    const int tid = threadIdx.x;
    const int lane = tid & 31, wid = tid >> 5;
    const float* zb = z + (size_t)b * FLATD;
    float s0 = 0.f, s1 = 0.f;
    for (int i = tid; i < FLATD; i += 256) {
        float zi = zb[i];
        s0 += zi * w[2 * i];
        s1 += zi * w[2 * i + 1];
    }
    for (int off = 16; off; off >>= 1) {
        s0 += __shfl_down_sync(0xffffffffu, s0, off);
        s1 += __shfl_down_sync(0xffffffffu, s1, off);
    }
    __shared__ float r0[8], r1[8];
    if (lane == 0) { r0[wid] = s0; r1[wid] = s1; }
    __syncthreads();
    if (tid == 0) {
        float z0 = bias[0], z1v = bias[1];
        #pragma unroll
        for (int i = 0; i < 8; i++) { z0 += r0[i]; z1v += r1[i]; }
        float m = fmaxf(z0, z1v);
        float e0 = expf(z0 - m), e1 = expf(z1v - m);
        float inv = 1.f / (e0 + e1);
        out[2 * b]     = e0 * inv;
        out[2 * b + 1] = e1 * inv;
    }
}

// ---------------- launch ----------------
extern "C" void kernel_launch(void* const* d_in, const int* in_sizes, int n_in,
                              void* d_out, int out_size)
{
    const float* x        = (const float*)d_in[0];
    const float* linear_w = (const float*)d_in[1];
    const float* linear_b = (const float*)d_in[2];
    const float* Wq = (const float*)d_in[3];
    const float* bq = (const float*)d_in[4];
    const float* Wk = (const float*)d_in[5];
    const float* bk = (const float*)d_in[6];
    const float* Wv = (const float*)d_in[7];
    const float* bv = (const float*)d_in[8];
    const float* Wo = (const float*)d_in[9];
    const float* bo = (const float*)d_in[10];
    const float* conv1_w = (const float*)d_in[11];
    const float* conv2_w = (const float*)d_in[12];
    const float* ln_w = (const float*)d_in[13];
    const float* ln_b = (const float*)d_in[14];
    const float* fc1_w = (const float*)d_in[15];
    const float* fc1_b = (const float*)d_in[16];
    const float* fc2_w = (const float*)d_in[17];
    const float* fc2_b = (const float*)d_in[18];
    const float* fc3_w = (const float*)d_in[19];
    const float* fc3_b = (const float*)d_in[20];

    float *h, *s, *t512, *z1, *wvo, *bvo, *bqkv;
    __half *w1h, *w1l, *w2h, *w2l, *eqh, *eql, *c1h, *c1l, *c2h, *c2l;
    cudaGetSymbolAddress((void**)&h,    g_h);
    cudaGetSymbolAddress((void**)&s,    g_s);
    cudaGetSymbolAddress((void**)&t512, g_t512);
    cudaGetSymbolAddress((void**)&z1,   g_z1);
    cudaGetSymbolAddress((void**)&wvo,  g_wvo);
    cudaGetSymbolAddress((void**)&bvo,  g_bvo);
    cudaGetSymbolAddress((void**)&bqkv, g_bqkv);
    cudaGetSymbolAddress((void**)&w1h,  g_w1h);
    cudaGetSymbolAddress((void**)&w1l,  g_w1l);
    cudaGetSymbolAddress((void**)&w2h,  g_w2h);
    cudaGetSymbolAddress((void**)&w2l,  g_w2l);
    cudaGetSymbolAddress((void**)&eqh,  g_eqh);
    cudaGetSymbolAddress((void**)&eql,  g_eql);
    cudaGetSymbolAddress((void**)&c1h,  g_c1h);
    cudaGetSymbolAddress((void**)&c1l,  g_c1l);
    cudaGetSymbolAddress((void**)&c2h,  g_c2h);
    cudaGetSymbolAddress((void**)&c2l,  g_c2l);

    cudaFuncSetAttribute(hgemm3_kernel<0,1,0>, cudaFuncAttributeMaxDynamicSharedMemorySize, HSM);
    cudaFuncSetAttribute(hgemm3_kernel<1,0,0>, cudaFuncAttributeMaxDynamicSharedMemorySize, HSM);
    cudaFuncSetAttribute(hgemm3_kernel<0,0,0>, cudaFuncAttributeMaxDynamicSharedMemorySize, HSM);
    cudaFuncSetAttribute(hgemm3_kernel<1,1,1>, cudaFuncAttributeMaxDynamicSharedMemorySize, HSM);
    cudaFuncSetAttribute(hgemm3_kernel<0,1,1>, cudaFuncAttributeMaxDynamicSharedMemorySize, HSM);

    const int BL = BSZ * SEQ;   // 147456

    // ---- prep (batched) ----
    tsplit_kernel<<<dim3(FC1N/32, FLATD/32, 1), dim3(32, 8)>>>(fc1_w, w1h, w1l, FLATD, FC1N, 0, 0);
    tsplit_kernel<<<dim3(FLATD/32, FC1N/32, 1), dim3(32, 8)>>>(fc2_w, w2h, w2l, FC1N, FLATD, 0, 0);
    wvo_gemm_kernel<<<NLAYER, 256>>>(Wv, Wo, wvo);
    bvo_kernel<<<NLAYER, 128>>>(bv, Wo, bo, bvo);
    packb_kernel<<<NLAYER, 384>>>(bq, bk, bvo, bqkv);
    // q, k, vo slots of the packed [3*DM][DM] per-layer planes (stride 3*DM*DM)
    tsplit_kernel<<<dim3(DM/32, DM/32, NLAYER), dim3(32, 8)>>>(Wq, eqh, eql, DM, DM,
                                                               (size_t)DM*DM, (size_t)3*DM*DM);
    tsplit_kernel<<<dim3(DM/32, DM/32, NLAYER), dim3(32, 8)>>>(Wk, eqh + DM*DM, eql + DM*DM, DM, DM,
                                                               (size_t)DM*DM, (size_t)3*DM*DM);
    tsplit_kernel<<<dim3(DM/32, DM/32, NLAYER), dim3(32, 8)>>>(wvo, eqh + 2*DM*DM, eql + 2*DM*DM, DM, DM,
                                                               (size_t)DM*DM, (size_t)3*DM*DM);
    tsplit_kernel<<<dim3(DFFN/32, DM/32, NLAYER), dim3(32, 8)>>>(conv1_w, c1h, c1l, DM, DFFN,
                                                                 (size_t)DM*DFFN, (size_t)DFFN*DM);
    tsplit_kernel<<<dim3(DM/32, DFFN/32, NLAYER), dim3(32, 8)>>>(conv2_w, c2h, c2l, DFFN, DM,
                                                                 (size_t)DFFN*DM, (size_t)DM*DFFN);

    // ---- embed (fp32: K=36) ----
    sgemm_kernel<0,1><<<dim3(FLATD/BN, BSZ/BM), 256>>>(x, linear_w, linear_b, h, BSZ, FLATD, 36);

    // ---- encoder: fused Q|K|VO GEMM -> autocorr+decomp -> FFN -> decomp ----
    for (int i = 0; i < NLAYER; i++) {
        const __half* wqkvh = eqh + (size_t)(i * 3) * DM * DM;   // [384][128]
        const __half* wqkvl = eql + (size_t)(i * 3) * DM * DM;
        const __half* w1hp = c1h + (size_t)i * DFFN * DM;
        const __half* w1lp = c1l + (size_t)i * DFFN * DM;
        const __half* w2hp = c2h + (size_t)i * DM * DFFN;
        const __half* w2lp = c2l + (size_t)i * DM * DFFN;

        hgemm3_kernel<0,1,0><<<(BL/256) * 3, 512, HSM>>>(h, wqkvh, wqkvl, bqkv + i*384, t512, BL, 384, DM, 3);
        autocorr_decomp_kernel<<<BSZ, 128>>>(t512, h);

        hgemm3_kernel<1,0,0><<<(BL/256) * (DFFN/128), 512, HSM>>>(h, w1hp, w1lp, nullptr, t512, BL, DFFN, DM, DFFN/128);
        hgemm3_kernel<0,0,0><<<BL/256, 512, HSM>>>(t512, w2hp, w2lp, nullptr, s, BL, DM, DFFN, 1);
        decomp_add_kernel<<<BSZ, 128>>>(h, s, h);
    }

    ln_kernel<<<BSZ, 128>>>(h, ln_w, ln_b, h);

    // ---- head: fc1 2-pass + fc2 2-pass (fp16(A) x exact B each) ----
    const int nbn1 = FC1N / 128;   // 108
    const int nbn2 = FLATD / 128;  // 36
    hgemm3_kernel<1,1,1><<<(BSZ/256) * nbn1, 512, HSM>>>(h, w1h, w1l, fc1_b, z1, BSZ, FC1N, FLATD, nbn1);
    hgemm3_kernel<0,1,1><<<(BSZ/256) * nbn2, 512, HSM>>>(z1, w2h, w2l, fc2_b, t512, BSZ, FLATD, FC1N, nbn2);
    fc3_softmax_kernel<<<BSZ, 256>>>(t512, fc3_w, fc3_b, (float*)d_out);
}

// round 16
// speedup vs baseline: 1.1538x; 1.1538x over previous
#include <cuda_runtime.h>
#include <cuda_fp16.h>
#include <math.h>
#include <stdint.h>

#define BSZ   4096
#define SEQ   36
#define DM    128
#define DFFN  512
#define NLAYER 8
#define FLATD (SEQ*DM)      // 4608
#define FC1N  13824

// ---------------- static scratch ----------------
__device__ float g_h  [(size_t)BSZ*FLATD];
__device__ float g_s  [(size_t)BSZ*FLATD];
__device__ float g_t512[(size_t)BSZ*SEQ*DFFN];   // QKV block [BL][384] / FFN scratch / z2
__device__ float g_z1 [(size_t)BSZ*FC1N];
__device__ float g_wvo[(size_t)NLAYER*DM*DM];    // Wv @ Wo per layer (fp32)
__device__ float g_bvo[(size_t)NLAYER*DM];
// fp16 hi/lo transposed weight planes [N][K]
__device__ __half g_w1h[(size_t)FC1N*FLATD];
__device__ __half g_w1l[(size_t)FC1N*FLATD];
__device__ __half g_w2h[(size_t)FLATD*FC1N];
__device__ __half g_w2l[(size_t)FLATD*FC1N];
// encoder weight planes: q,k,vo per layer [384][128] packed; conv1 [512][128]; conv2 [128][512]
__device__ __half g_eqh[(size_t)NLAYER*3*DM*DM];
__device__ __half g_eql[(size_t)NLAYER*3*DM*DM];
__device__ __half g_c1h[(size_t)NLAYER*DFFN*DM];
__device__ __half g_c1l[(size_t)NLAYER*DFFN*DM];
__device__ __half g_c2h[(size_t)NLAYER*DM*DFFN];
__device__ __half g_c2l[(size_t)NLAYER*DM*DFFN];
__device__ float  g_bqkv[(size_t)NLAYER*384];

// ============================================================================
// fp32 SGEMM — embed only (K=36)
// ============================================================================
#define BM 128
#define BN 128
#define BK 16
#define PADA 17

template<int DO_GELU, int HAS_BIAS>
__global__ __launch_bounds__(256, 2)
void sgemm_kernel(const float* __restrict__ A, const float* __restrict__ W,
                  const float* __restrict__ bias, float* __restrict__ C,
                  int M, int N, int K)
{
    __shared__ float As[BM][PADA];
    __shared__ float Ws[BK][BN];

    const int tid = threadIdx.x;
    const int tx  = tid & 15;
    const int ty  = tid >> 4;
    const size_t bm = blockIdx.y;
    const size_t bn = blockIdx.x;

    const float* Ab = A + bm * BM * (size_t)K;
    const float* Wb = W + bn * BN;

    float acc[8][8];
    #pragma unroll
    for (int i = 0; i < 8; i++)
        #pragma unroll
        for (int j = 0; j < 8; j++) acc[i][j] = 0.f;

    const int ka = tid & 15;
    const int ma = tid >> 4;
    const int nw = tid & 127;
    const int kw = tid >> 7;

    for (int k0 = 0; k0 < K; k0 += BK) {
        const bool kaok = (k0 + ka) < K;
        #pragma unroll
        for (int i = 0; i < 8; i++) {
            int m = ma + i * 16;
            float val = 0.f;
            if (kaok) val = Ab[(size_t)m * K + k0 + ka];
            As[m][ka] = val;
        }
        #pragma unroll
        for (int i = 0; i < 8; i++) {
            int kk = kw + i * 2;
            float val = 0.f;
            if (k0 + kk < K) val = Wb[(size_t)(k0 + kk) * N + nw];
            Ws[kk][nw] = val;
        }
        __syncthreads();

        #pragma unroll
        for (int kk = 0; kk < BK; kk++) {
            float ar[8];
            #pragma unroll
            for (int i = 0; i < 8; i++) ar[i] = As[ty * 8 + i][kk];
            float4 b0 = *(const float4*)&Ws[kk][tx * 8];
            float4 b1 = *(const float4*)&Ws[kk][tx * 8 + 4];
            float br[8] = {b0.x, b0.y, b0.z, b0.w, b1.x, b1.y, b1.z, b1.w};
            #pragma unroll
            for (int i = 0; i < 8; i++)
                #pragma unroll
                for (int j = 0; j < 8; j++)
                    acc[i][j] += ar[i] * br[j];
        }
        __syncthreads();
    }

    float bv[8];
    #pragma unroll
    for (int j = 0; j < 8; j++) bv[j] = 0.f;
    if (HAS_BIAS) {
        #pragma unroll
        for (int j = 0; j < 8; j++) bv[j] = bias[bn * BN + tx * 8 + j];
    }

    #pragma unroll
    for (int i = 0; i < 8; i++) {
        size_t row = bm * BM + ty * 8 + i;
        float* Cp = C + row * (size_t)N + bn * BN + tx * 8;
        float o[8];
        #pragma unroll
        for (int j = 0; j < 8; j++) {
            float vv = acc[i][j] + bv[j];
            if (DO_GELU) vv = 0.5f * vv * (1.f + erff(vv * 0.70710678118654752f));
            o[j] = vv;
        }
        *(float4*)Cp       = make_float4(o[0], o[1], o[2], o[3]);
        *(float4*)(Cp + 4) = make_float4(o[4], o[5], o[6], o[7]);
    }
}

// ============================================================================
// batched Wvo = Wv @ Wo (fp32 exact, one 128x128 block per layer)
// ============================================================================
__global__ __launch_bounds__(256, 2)
void wvo_gemm_kernel(const float* __restrict__ Wv, const float* __restrict__ Wo,
                     float* __restrict__ Cout)
{
    __shared__ float As[BM][PADA];
    __shared__ float Ws[BK][BN];

    const int tid = threadIdx.x;
    const int tx  = tid & 15;
    const int ty  = tid >> 4;
    const size_t lay = blockIdx.x;
    const float* Ab = Wv + lay * DM * DM;
    const float* Wb = Wo + lay * DM * DM;
    float* C = Cout + lay * DM * DM;

    float acc[8][8];
    #pragma unroll
    for (int i = 0; i < 8; i++)
        #pragma unroll
        for (int j = 0; j < 8; j++) acc[i][j] = 0.f;

    const int ka = tid & 15;
    const int ma = tid >> 4;
    const int nw = tid & 127;
    const int kw = tid >> 7;

    for (int k0 = 0; k0 < DM; k0 += BK) {
        #pragma unroll
        for (int i = 0; i < 8; i++) {
            int m = ma + i * 16;
            As[m][ka] = Ab[(size_t)m * DM + k0 + ka];
        }
        #pragma unroll
        for (int i = 0; i < 8; i++) {
            int kk = kw + i * 2;
            Ws[kk][nw] = Wb[(size_t)(k0 + kk) * DM + nw];
        }
        __syncthreads();

        #pragma unroll
        for (int kk = 0; kk < BK; kk++) {
            float ar[8];
            #pragma unroll
            for (int i = 0; i < 8; i++) ar[i] = As[ty * 8 + i][kk];
            float4 b0 = *(const float4*)&Ws[kk][tx * 8];
            float4 b1 = *(const float4*)&Ws[kk][tx * 8 + 4];
            float br[8] = {b0.x, b0.y, b0.z, b0.w, b1.x, b1.y, b1.z, b1.w};
            #pragma unroll
            for (int i = 0; i < 8; i++)
                #pragma unroll
                for (int j = 0; j < 8; j++)
                    acc[i][j] += ar[i] * br[j];
        }
        __syncthreads();
    }

    #pragma unroll
    for (int i = 0; i < 8; i++) {
        size_t row = ty * 8 + i;
        float* Cp = C + row * DM + tx * 8;
        *(float4*)Cp       = make_float4(acc[i][0], acc[i][1], acc[i][2], acc[i][3]);
        *(float4*)(Cp + 4) = make_float4(acc[i][4], acc[i][5], acc[i][6], acc[i][7]);
    }
}

// ============================================================================
// prep kernels (layer-batched)
// ============================================================================
__global__ __launch_bounds__(256)
void tsplit_kernel(const float* __restrict__ src, __half* __restrict__ dh,
                   __half* __restrict__ dl, int K, int N,
                   size_t srcStride, size_t dstStride)
{
    __shared__ float t[32][33];
    const size_t z = blockIdx.z;
    const float* s = src + z * srcStride;
    __half* dhh = dh + z * dstStride;
    __half* dll = dl + z * dstStride;
    const int n0 = blockIdx.x * 32, k0 = blockIdx.y * 32;
    const int tx = threadIdx.x, ty = threadIdx.y;   // 32 x 8
    #pragma unroll
    for (int j = 0; j < 32; j += 8)
        t[ty + j][tx] = s[(size_t)(k0 + ty + j) * N + n0 + tx];
    __syncthreads();
    #pragma unroll
    for (int j = 0; j < 32; j += 8) {
        float v = t[tx][ty + j];
        __half h = __float2half_rn(v);
        const size_t o = (size_t)(n0 + ty + j) * K + k0 + tx;
        dhh[o] = h;
        dll[o] = __float2half_rn(v - __half2float(h));
    }
}

// coalesced bvo: one block, 8 warps -> each warp handles 1 layer's 128 outputs
// via 4 j-chunks of 32; rows of Wo read coalesced. Same per-output FMA order.
__global__ __launch_bounds__(256)
void bvo_kernel(const float* __restrict__ bv, const float* __restrict__ Wo,
                const float* __restrict__ bo, float* __restrict__ bvo)
{
    const int i = blockIdx.x;           // layer
    const int j = threadIdx.x;          // 0..127 output col
    __shared__ float bs[DM];
    if (j < DM) bs[j] = bv[i * DM + j];
    __syncthreads();
    const float* wop = Wo + (size_t)i * DM * DM + j;
    float s = 0.f;
    #pragma unroll 8
    for (int k = 0; k < DM; k++) s += bs[k] * wop[(size_t)k * DM];
    bvo[i * DM + j] = s + bo[i * DM + j];
}

__global__ __launch_bounds__(384)
void packb_kernel(const float* __restrict__ bq, const float* __restrict__ bk,
                  const float* __restrict__ bvo, float* __restrict__ dst)
{
    const int i = blockIdx.x;
    const int t = threadIdx.x;
    float v = (t < 128) ? bq[i * 128 + t]
            : (t < 256) ? bk[i * 128 + t - 128]
                        : bvo[i * 128 + t - 256];
    dst[i * 384 + t] = v;
}

// ============================================================================
// 3xFP16 tensor-core GEMM v3 (PROVEN R14 config: 256 thr, M=128, 2 CTA/SM).
// TWO_PASS=1 (head): drop Al*Bh pass -> fp16(A) x exact B.
// ============================================================================
#define USTR  20
#define PLANE (128*USTR)
#define STAGE (4*PLANE)
#define HSM   (2*STAGE*4)

__device__ __forceinline__ uint32_t packh(__half a, __half b) {
    __half2 t = __halves2half2(a, b);
    return *reinterpret_cast<uint32_t*>(&t);
}
__device__ __forceinline__ uint32_t smem_u32p(const void* p) {
    uint32_t a;
    asm("{ .reg .u64 t; cvta.to.shared.u64 t, %1; cvt.u32.u64 %0, t; }" : "=r"(a) : "l"(p));
    return a;
}
__device__ __forceinline__ void cp16(uint32_t dst, const void* src) {
    asm volatile("cp.async.cg.shared.global [%0], [%1], 16;" :: "r"(dst), "l"(src) : "memory");
}

#define LDSM4(R0, R1, R2, R3, ADDR)                                              \
    asm volatile("ldmatrix.sync.aligned.m8n8.x4.shared.b16 {%0,%1,%2,%3}, [%4];" \
        : "=r"(R0), "=r"(R1), "=r"(R2), "=r"(R3) : "r"(ADDR))

#define MMA_F16(ACC, A0, A1, A2, A3, B0, B1)                                    \
    asm volatile(                                                                \
        "mma.sync.aligned.m16n8k16.row.col.f32.f16.f16.f32 "                    \
        "{%0,%1,%2,%3}, {%4,%5,%6,%7}, {%8,%9}, {%0,%1,%2,%3};\n"               \
        : "+f"(ACC[0]), "+f"(ACC[1]), "+f"(ACC[2]), "+f"(ACC[3])                \
        : "r"(A0), "r"(A1), "r"(A2), "r"(A3), "r"(B0), "r"(B1))

template<int DO_GELU, int HAS_BIAS, int TWO_PASS>
__global__ __launch_bounds__(256, 2)
void hgemm3_kernel(const float* __restrict__ A, const __half* __restrict__ Wh,
                   const __half* __restrict__ Wl, const float* __restrict__ bias,
                   float* __restrict__ C, int M, int N, int K, int nbn)
{
    extern __shared__ uint32_t smem[];

    const int tid  = threadIdx.x;
    const int warp = tid >> 5;
    const int lane = tid & 31;
    const int wm = warp >> 2;
    const int wn = warp & 3;
    const int g  = lane >> 2;
    const int t4 = lane & 3;

    const int per = 8 * nbn;
    const int bm = (blockIdx.x / per) * 8 + (blockIdx.x % per) % 8;
    const int bn = (blockIdx.x % per) / 8;
    const size_t bm0 = (size_t)bm * 128;
    const int bn0 = bn * 128;

    const int lrow = tid >> 1;
    const int o0   = (tid & 1) * 8;
    const int khal = o0 * 2;
    const float*  ap  = A  + (bm0 + lrow) * (size_t)K + khal;
    const __half* bph = Wh + (size_t)(bn0 + lrow) * K + khal;
    const __half* bpl = Wl + (size_t)(bn0 + lrow) * K + khal;

    const uint32_t smb = smem_u32p(smem);
    const int boff = lrow * USTR + o0;

    const int l15 = lane & 15;
    const uint32_t a_base = ((uint32_t)(wm * 64 + l15) * USTR + (lane >> 4) * 4) * 4;
    const int bl7 = (lane & 7) + ((lane >> 4) << 3);
    const uint32_t b_base = ((uint32_t)(wn * 32 + bl7) * USTR + ((lane >> 3) & 1) * 4) * 4;

    float acc[4][4][4];
    #pragma unroll
    for (int mi = 0; mi < 4; mi++)
        #pragma unroll
        for (int ni = 0; ni < 4; ni++)
            #pragma unroll
            for (int r = 0; r < 4; r++) acc[mi][ni][r] = 0.f;

    // ---- prologue: stage 0 ----
    {
        const uint32_t dBh = smb + (2 * PLANE + boff) * 4;
        const uint32_t dBl = smb + (3 * PLANE + boff) * 4;
        cp16(dBh,      bph);     cp16(dBh + 16, bph + 8);
        cp16(dBl,      bpl);     cp16(dBl + 16, bpl + 8);
        asm volatile("cp.async.commit_group;" ::: "memory");

        float4 pa0 = *(const float4*)(ap);
        float4 pa1 = *(const float4*)(ap + 4);
        float4 pa2 = *(const float4*)(ap + 8);
        float4 pa3 = *(const float4*)(ap + 12);
        float fv[16] = {pa0.x, pa0.y, pa0.z, pa0.w, pa1.x, pa1.y, pa1.z, pa1.w,
                        pa2.x, pa2.y, pa2.z, pa2.w, pa3.x, pa3.y, pa3.z, pa3.w};
        uint32_t uh[8], ul[8];
        #pragma unroll
        for (int j = 0; j < 8; j++) {
            float a0 = fv[2 * j], a1 = fv[2 * j + 1];
            __half h0 = __float2half_rn(a0), h1 = __float2half_rn(a1);
            uh[j] = packh(h0, h1);
            if (!TWO_PASS)
                ul[j] = packh(__float2half_rn(a0 - __half2float(h0)),
                              __float2half_rn(a1 - __half2float(h1)));
        }
        *(uint4*)&smem[boff]             = make_uint4(uh[0], uh[1], uh[2], uh[3]);
        *(uint4*)&smem[boff + 4]         = make_uint4(uh[4], uh[5], uh[6], uh[7]);
        if (!TWO_PASS) {
            *(uint4*)&smem[PLANE + boff]     = make_uint4(ul[0], ul[1], ul[2], ul[3]);
            *(uint4*)&smem[PLANE + boff + 4] = make_uint4(ul[4], ul[5], ul[6], ul[7]);
        }
        asm volatile("cp.async.wait_group 0;" ::: "memory");
    }
    __syncthreads();

    float4 pa0, pa1, pa2, pa3;
    int it = 0;
    for (int k0 = 0; k0 < K; k0 += 32, it++) {
        const int cur = it & 1;
        const int nxt = cur ^ 1;
        const bool more = (k0 + 32) < K;

        if (more) {
            const int kn = k0 + 32;
            const uint32_t dBh = smb + (nxt * STAGE + 2 * PLANE + boff) * 4;
            const uint32_t dBl = smb + (nxt * STAGE + 3 * PLANE + boff) * 4;
            cp16(dBh,      bph + kn);     cp16(dBh + 16, bph + kn + 8);
            cp16(dBl,      bpl + kn);     cp16(dBl + 16, bpl + kn + 8);
            asm volatile("cp.async.commit_group;" ::: "memory");
            pa0 = *(const float4*)(ap + kn);
            pa1 = *(const float4*)(ap + kn + 4);
            pa2 = *(const float4*)(ap + kn + 8);
            pa3 = *(const float4*)(ap + kn + 12);
        }

        const uint32_t stb = smb + cur * STAGE * 4;
        #pragma unroll
        for (int ks = 0; ks < 2; ks++) {
            const uint32_t kbb = ks * 32;
            uint32_t af[4][4], al_[4][4], bf[4][2], bt[4][2];
            #pragma unroll
            for (int mi = 0; mi < 4; mi++) {
                const uint32_t ao = stb + a_base + (uint32_t)(mi * 16 * USTR) * 4 + kbb;
                LDSM4(af[mi][0], af[mi][1], af[mi][2], af[mi][3], ao);
                if (!TWO_PASS)
                    LDSM4(al_[mi][0], al_[mi][1], al_[mi][2], al_[mi][3], ao + PLANE * 4);
            }
            {
                const uint32_t bo0 = stb + (2 * PLANE) * 4 + b_base + kbb;
                const uint32_t bo1 = bo0 + (uint32_t)(16 * USTR) * 4;
                LDSM4(bf[0][0], bf[0][1], bf[1][0], bf[1][1], bo0);
                LDSM4(bf[2][0], bf[2][1], bf[3][0], bf[3][1], bo1);
                LDSM4(bt[0][0], bt[0][1], bt[1][0], bt[1][1], bo0 + PLANE * 4);
                LDSM4(bt[2][0], bt[2][1], bt[3][0], bt[3][1], bo1 + PLANE * 4);
            }
            #pragma unroll
            for (int mi = 0; mi < 4; mi++)
                #pragma unroll
                for (int ni = 0; ni < 4; ni++)
                    MMA_F16(acc[mi][ni], af[mi][0], af[mi][1], af[mi][2], af[mi][3],
                            bf[ni][0], bf[ni][1]);
            #pragma unroll
            for (int mi = 0; mi < 4; mi++)
                #pragma unroll
                for (int ni = 0; ni < 4; ni++)
                    MMA_F16(acc[mi][ni], af[mi][0], af[mi][1], af[mi][2], af[mi][3],
                            bt[ni][0], bt[ni][1]);
            if (!TWO_PASS) {
                #pragma unroll
                for (int mi = 0; mi < 4; mi++)
                    #pragma unroll
                    for (int ni = 0; ni < 4; ni++)
                        MMA_F16(acc[mi][ni], al_[mi][0], al_[mi][1], al_[mi][2], al_[mi][3],
                                bf[ni][0], bf[ni][1]);
            }
        }

        if (more) {
            float fv[16] = {pa0.x, pa0.y, pa0.z, pa0.w, pa1.x, pa1.y, pa1.z, pa1.w,
                            pa2.x, pa2.y, pa2.z, pa2.w, pa3.x, pa3.y, pa3.z, pa3.w};
            uint32_t uh[8], ul[8];
            #pragma unroll
            for (int j = 0; j < 8; j++) {
                float a0 = fv[2 * j], a1 = fv[2 * j + 1];
                __half h0 = __float2half_rn(a0), h1 = __float2half_rn(a1);
                uh[j] = packh(h0, h1);
                if (!TWO_PASS)
                    ul[j] = packh(__float2half_rn(a0 - __half2float(h0)),
                                  __float2half_rn(a1 - __half2float(h1)));
            }
            uint32_t* sb = smem + nxt * STAGE;
            *(uint4*)&sb[boff]             = make_uint4(uh[0], uh[1], uh[2], uh[3]);
            *(uint4*)&sb[boff + 4]         = make_uint4(uh[4], uh[5], uh[6], uh[7]);
            if (!TWO_PASS) {
                *(uint4*)&sb[PLANE + boff]     = make_uint4(ul[0], ul[1], ul[2], ul[3]);
                *(uint4*)&sb[PLANE + boff + 4] = make_uint4(ul[4], ul[5], ul[6], ul[7]);
            }
            asm volatile("cp.async.wait_group 0;" ::: "memory");
        }
        __syncthreads();
    }

    // epilogue
    #pragma unroll
    for (int ni = 0; ni < 4; ni++) {
        const int col = bn0 + wn * 32 + ni * 8 + 2 * t4;
        float b0 = 0.f, b1 = 0.f;
        if (HAS_BIAS) { b0 = bias[col]; b1 = bias[col + 1]; }
        #pragma unroll
        for (int mi = 0; mi < 4; mi++) {
            #pragma unroll
            for (int hh = 0; hh < 2; hh++) {
                const size_t row = bm0 + wm * 64 + mi * 16 + g + hh * 8;
                float v0 = acc[mi][ni][2 * hh]     + b0;
                float v1 = acc[mi][ni][2 * hh + 1] + b1;
                if (DO_GELU) {
                    v0 = 0.5f * v0 * (1.f + erff(v0 * 0.70710678118654752f));
                    v1 = 0.5f * v1 * (1.f + erff(v1 * 0.70710678118654752f));
                }
                *(float2*)(C + row * (size_t)N + col) = make_float2(v0, v1);
            }
        }
    }
}

// ============================================================================
// AutoCorrelation + fused series_decomp residual (reads QKV [BL][384])
// ============================================================================
__global__ __launch_bounds__(128)
void autocorr_decomp_kernel(const float* __restrict__ QKV, float* __restrict__ H)
{
    const int b = blockIdx.x;
    const int c = threadIdx.x;
    const size_t qbase = (size_t)b * SEQ * 384 + c;
    const size_t obase = (size_t)b * FLATD + c;

    float qr[SEQ], kr[SEQ];
    #pragma unroll
    for (int t = 0; t < SEQ; t++) {
        qr[t] = QKV[qbase + (size_t)t * 384];
        kr[t] = QKV[qbase + (size_t)t * 384 + 128];
    }

    float acc[SEQ];
    #pragma unroll
    for (int tau = 0; tau < SEQ; tau++) {
        float s = 0.f;
        #pragma unroll
        for (int t = 0; t < SEQ; t++) s += qr[t] * kr[(t + SEQ - tau) % SEQ];
        acc[tau] = s;
    }

    const int lane = c & 31, wid = c >> 5;
    __shared__ float red[SEQ][4];
    #pragma unroll
    for (int tau = 0; tau < SEQ; tau++) {
        float s = acc[tau];
        s += __shfl_down_sync(0xffffffffu, s, 16);
        s += __shfl_down_sync(0xffffffffu, s, 8);
        s += __shfl_down_sync(0xffffffffu, s, 4);
        s += __shfl_down_sync(0xffffffffu, s, 2);
        s += __shfl_down_sync(0xffffffffu, s, 1);
        if (lane == 0) red[tau][wid] = s;
    }
    __syncthreads();

    __shared__ float corr[SEQ];
    if (c < SEQ) corr[c] = (red[c][0] + red[c][1] + red[c][2] + red[c][3]) * (1.f / 128.f);
    __syncthreads();

    __shared__ float wsm[3];
    __shared__ int   dsm[3];
    if (c == 0) {
        float tmp[SEQ];
        for (int t = 0; t < SEQ; t++) tmp[t] = corr[t];
        float wv[3]; int dv[3];
        for (int r = 0; r < 3; r++) {
            float best = tmp[0]; int bi = 0;
            for (int t = 1; t < SEQ; t++)
                if (tmp[t] > best) { best = tmp[t]; bi = t; }
            wv[r] = best; dv[r] = bi;
            tmp[bi] = -1e30f;
        }
        float m = wv[0];
        float e0 = expf(wv[0] - m), e1 = expf(wv[1] - m), e2 = expf(wv[2] - m);
        float inv = 1.f / (e0 + e1 + e2);
        wsm[0] = e0 * inv; wsm[1] = e1 * inv; wsm[2] = e2 * inv;
        dsm[0] = dv[0]; dsm[1] = dv[1]; dsm[2] = dv[2];
    }
    __syncthreads();

    const float w0 = wsm[0], w1 = wsm[1], w2 = wsm[2];
    const int   d0 = dsm[0], d1 = dsm[1], d2 = dsm[2];
    const float* vb = QKV + qbase + 256;

    float p[SEQ];
    #pragma unroll
    for (int t = 0; t < SEQ; t++) {
        int j0 = t + d0; if (j0 >= SEQ) j0 -= SEQ;
        int j1 = t + d1; if (j1 >= SEQ) j1 -= SEQ;
        int j2 = t + d2; if (j2 >= SEQ) j2 -= SEQ;
        float a = w0 * vb[(size_t)j0 * 384] + w1 * vb[(size_t)j1 * 384]
                + w2 * vb[(size_t)j2 * 384];
        p[t] = H[obase + (size_t)t * DM] + a;
    }

    float run = 12.f * p[0];
    #pragma unroll
    for (int j = 0; j <= 12; j++) run += p[j];
    #pragma unroll
    for (int t = 0; t < SEQ; t++) {
        H[obase + (size_t)t * DM] = p[t] - run * (1.f / 25.f);
        int jn = t + 13; if (jn > SEQ - 1) jn = SEQ - 1;
        int jo = t - 12; if (jo < 0) jo = 0;
        run += p[jn] - p[jo];
    }
}

// ---------------- series_decomp with fused residual add (FFN branch) ----------------
__global__ __launch_bounds__(128)
void decomp_add_kernel(const float* __restrict__ hin, const float* __restrict__ sin_,
                       float* __restrict__ hout)
{
    const int b = blockIdx.x;
    const int c = threadIdx.x;
    __shared__ float p[SEQ][DM];
    const size_t base = (size_t)b * FLATD + c;
    #pragma unroll
    for (int t = 0; t < SEQ; t++)
        p[t][c] = hin[base + t * DM] + sin_[base + t * DM];
    __syncthreads();

    float run = 12.f * p[0][c];
    #pragma unroll
    for (int j = 0; j <= 12; j++) run += p[j][c];
    #pragma unroll
    for (int t = 0; t < SEQ; t++) {
        hout[base + t * DM] = p[t][c] - run * (1.f / 25.f);
        int jn = t + 13; if (jn > SEQ - 1) jn = SEQ - 1;
        int jo = t - 12; if (jo < 0) jo = 0;
        run += p[jn][c] - p[jo][c];
    }
}

// ---------------- my_Layernorm ----------------
__global__ __launch_bounds__(128)
void ln_kernel(const float* __restrict__ hin, const float* __restrict__ lnw,
               const float* __restrict__ lnb, float* __restrict__ hout)
{
    const int b = blockIdx.x;
    const int c = threadIdx.x;
    const int lane = c & 31, wid = c >> 5;
    __shared__ float xs[SEQ][DM];
    __shared__ float r1[4], r2[4];
    const size_t base = (size_t)b * FLATD + c;
    #pragma unroll
    for (int t = 0; t < SEQ; t++) xs[t][c] = hin[base + t * DM];
    __syncthreads();

    const float gw = lnw[c], gb = lnb[c];
    for (int t = 0; t < SEQ; t++) {
        float val = xs[t][c];
        float s = val;
        s += __shfl_down_sync(0xffffffffu, s, 16);
        s += __shfl_down_sync(0xffffffffu, s, 8);
        s += __shfl_down_sync(0xffffffffu, s, 4);
        s += __shfl_down_sync(0xffffffffu, s, 2);
        s += __shfl_down_sync(0xffffffffu, s, 1);
        if (lane == 0) r1[wid] = s;
        __syncthreads();
        float mean = (r1[0] + r1[1] + r1[2] + r1[3]) * (1.f / 128.f);
        float d = val - mean;
        float sq = d * d;
        sq += __shfl_down_sync(0xffffffffu, sq, 16);
        sq += __shfl_down_sync(0xffffffffu, sq, 8);
        sq += __shfl_down_sync(0xffffffffu, sq, 4);
        sq += __shfl_down_sync(0xffffffffu, sq, 2);
        sq += __shfl_down_sync(0xffffffffu, sq, 1);
        if (lane == 0) r2[wid] = sq;
        __syncthreads();
        float var = (r2[0] + r2[1] + r2[2] + r2[3]) * (1.f / 128.f);
        xs[t][c] = d * (1.f / sqrtf(var + 1e-5f)) * gw + gb;
    }
    float cm = 0.f;
    #pragma unroll
    for (int t = 0; t < SEQ; t++) cm += xs[t][c];
    cm *= (1.f / 36.f);
    #pragma unroll
    for (int t = 0; t < SEQ; t++)
        hout[base + t * DM] = xs[t][c] - cm;
}

// ---------------- fc3 [4608 -> 2] + softmax ----------------
__global__ __launch_bounds__(256)
void fc3_softmax_kernel(const float* __restrict__ z, const float* __restrict__ w,
                        const float* __restrict__ bias, float* __restrict__ out)
{
    const int b = blockIdx.x;
    const int tid = threadIdx.x;
    const int lane = tid & 31, wid = tid >> 5;
    const float* zb = z + (size_t)b * FLATD;
    float s0 = 0.f, s1 = 0.f;
    for (int i = tid; i < FLATD; i += 256) {
        float zi = zb[i];
        s0 += zi * w[2 * i];
        s1 += zi * w[2 * i + 1];
    }
    for (int off = 16; off; off >>= 1) {
        s0 += __shfl_down_sync(0xffffffffu, s0, off);
        s1 += __shfl_down_sync(0xffffffffu, s1, off);
    }
    __shared__ float r0[8], r1[8];
    if (lane == 0) { r0[wid] = s0; r1[wid] = s1; }
    __syncthreads();
    if (tid == 0) {
        float z0 = bias[0], z1v = bias[1];
        #pragma unroll
        for (int i = 0; i < 8; i++) { z0 += r0[i]; z1v += r1[i]; }
        float m = fmaxf(z0, z1v);
        float e0 = expf(z0 - m), e1 = expf(z1v - m);
        float inv = 1.f / (e0 + e1);
        out[2 * b]     = e0 * inv;
        out[2 * b + 1] = e1 * inv;
    }
}

// ---------------- launch ----------------
extern "C" void kernel_launch(void* const* d_in, const int* in_sizes, int n_in,
                              void* d_out, int out_size)
{
    const float* x        = (const float*)d_in[0];
    const float* linear_w = (const float*)d_in[1];
    const float* linear_b = (const float*)d_in[2];
    const float* Wq = (const float*)d_in[3];
    const float* bq = (const float*)d_in[4];
    const float* Wk = (const float*)d_in[5];
    const float* bk = (const float*)d_in[6];
    const float* Wv = (const float*)d_in[7];
    const float* bv = (const float*)d_in[8];
    const float* Wo = (const float*)d_in[9];
    const float* bo = (const float*)d_in[10];
    const float* conv1_w = (const float*)d_in[11];
    const float* conv2_w = (const float*)d_in[12];
    const float* ln_w = (const float*)d_in[13];
    const float* ln_b = (const float*)d_in[14];
    const float* fc1_w = (const float*)d_in[15];
    const float* fc1_b = (const float*)d_in[16];
    const float* fc2_w = (const float*)d_in[17];
    const float* fc2_b = (const float*)d_in[18];
    const float* fc3_w = (const float*)d_in[19];
    const float* fc3_b = (const float*)d_in[20];

    float *h, *s, *t512, *z1, *wvo, *bvo, *bqkv;
    __half *w1h, *w1l, *w2h, *w2l, *eqh, *eql, *c1h, *c1l, *c2h, *c2l;
    cudaGetSymbolAddress((void**)&h,    g_h);
    cudaGetSymbolAddress((void**)&s,    g_s);
    cudaGetSymbolAddress((void**)&t512, g_t512);
    cudaGetSymbolAddress((void**)&z1,   g_z1);
    cudaGetSymbolAddress((void**)&wvo,  g_wvo);
    cudaGetSymbolAddress((void**)&bvo,  g_bvo);
    cudaGetSymbolAddress((void**)&bqkv, g_bqkv);
    cudaGetSymbolAddress((void**)&w1h,  g_w1h);
    cudaGetSymbolAddress((void**)&w1l,  g_w1l);
    cudaGetSymbolAddress((void**)&w2h,  g_w2h);
    cudaGetSymbolAddress((void**)&w2l,  g_w2l);
    cudaGetSymbolAddress((void**)&eqh,  g_eqh);
    cudaGetSymbolAddress((void**)&eql,  g_eql);
    cudaGetSymbolAddress((void**)&c1h,  g_c1h);
    cudaGetSymbolAddress((void**)&c1l,  g_c1l);
    cudaGetSymbolAddress((void**)&c2h,  g_c2h);
    cudaGetSymbolAddress((void**)&c2l,  g_c2l);

    cudaFuncSetAttribute(hgemm3_kernel<0,1,0>, cudaFuncAttributeMaxDynamicSharedMemorySize, HSM);
    cudaFuncSetAttribute(hgemm3_kernel<1,0,0>, cudaFuncAttributeMaxDynamicSharedMemorySize, HSM);
    cudaFuncSetAttribute(hgemm3_kernel<0,0,0>, cudaFuncAttributeMaxDynamicSharedMemorySize, HSM);
    cudaFuncSetAttribute(hgemm3_kernel<1,1,1>, cudaFuncAttributeMaxDynamicSharedMemorySize, HSM);
    cudaFuncSetAttribute(hgemm3_kernel<0,1,1>, cudaFuncAttributeMaxDynamicSharedMemorySize, HSM);

    const int BL = BSZ * SEQ;   // 147456

    // ---- prep (batched) ----
    tsplit_kernel<<<dim3(FC1N/32, FLATD/32, 1), dim3(32, 8)>>>(fc1_w, w1h, w1l, FLATD, FC1N, 0, 0);
    tsplit_kernel<<<dim3(FLATD/32, FC1N/32, 1), dim3(32, 8)>>>(fc2_w, w2h, w2l, FC1N, FLATD, 0, 0);
    wvo_gemm_kernel<<<NLAYER, 256>>>(Wv, Wo, wvo);
    bvo_kernel<<<NLAYER, 128>>>(bv, Wo, bo, bvo);
    packb_kernel<<<NLAYER, 384>>>(bq, bk, bvo, bqkv);
    tsplit_kernel<<<dim3(DM/32, DM/32, NLAYER), dim3(32, 8)>>>(Wq, eqh, eql, DM, DM,
                                                               (size_t)DM*DM, (size_t)3*DM*DM);
    tsplit_kernel<<<dim3(DM/32, DM/32, NLAYER), dim3(32, 8)>>>(Wk, eqh + DM*DM, eql + DM*DM, DM, DM,
                                                               (size_t)DM*DM, (size_t)3*DM*DM);
    tsplit_kernel<<<dim3(DM/32, DM/32, NLAYER), dim3(32, 8)>>>(wvo, eqh + 2*DM*DM, eql + 2*DM*DM, DM, DM,
                                                               (size_t)DM*DM, (size_t)3*DM*DM);
    tsplit_kernel<<<dim3(DFFN/32, DM/32, NLAYER), dim3(32, 8)>>>(conv1_w, c1h, c1l, DM, DFFN,
                                                                 (size_t)DM*DFFN, (size_t)DFFN*DM);
    tsplit_kernel<<<dim3(DM/32, DFFN/32, NLAYER), dim3(32, 8)>>>(conv2_w, c2h, c2l, DFFN, DM,
                                                                 (size_t)DFFN*DM, (size_t)DM*DFFN);

    // ---- embed (fp32: K=36) ----
    sgemm_kernel<0,1><<<dim3(FLATD/BN, BSZ/BM), 256>>>(x, linear_w, linear_b, h, BSZ, FLATD, 36);

    // ---- encoder: fused Q|K|VO GEMM -> autocorr+decomp -> FFN -> decomp ----
    for (int i = 0; i < NLAYER; i++) {
        const __half* wqkvh = eqh + (size_t)(i * 3) * DM * DM;   // [384][128]
        const __half* wqkvl = eql + (size_t)(i * 3) * DM * DM;
        const __half* w1hp = c1h + (size_t)i * DFFN * DM;
        const __half* w1lp = c1l + (size_t)i * DFFN * DM;
        const __half* w2hp = c2h + (size_t)i * DM * DFFN;
        const __half* w2lp = c2l + (size_t)i * DM * DFFN;

        hgemm3_kernel<0,1,0><<<(BL/128) * 3, 256, HSM>>>(h, wqkvh, wqkvl, bqkv + i*384, t512, BL, 384, DM, 3);
        autocorr_decomp_kernel<<<BSZ, 128>>>(t512, h);

        hgemm3_kernel<1,0,0><<<(BL/128) * (DFFN/128), 256, HSM>>>(h, w1hp, w1lp, nullptr, t512, BL, DFFN, DM, DFFN/128);
        hgemm3_kernel<0,0,0><<<BL/128, 256, HSM>>>(t512, w2hp, w2lp, nullptr, s, BL, DM, DFFN, 1);
        decomp_add_kernel<<<BSZ, 128>>>(h, s, h);
    }

    ln_kernel<<<BSZ, 128>>>(h, ln_w, ln_b, h);

    // ---- head: fc1 2-pass + fc2 2-pass (fp16(A) x exact B each) ----
    const int nbn1 = FC1N / 128;   // 108
    const int nbn2 = FLATD / 128;  // 36
    hgemm3_kernel<1,1,1><<<(BSZ/128) * nbn1, 256, HSM>>>(h, w1h, w1l, fc1_b, z1, BSZ, FC1N, FLATD, nbn1);
    hgemm3_kernel<0,1,1><<<(BSZ/128) * nbn2, 256, HSM>>>(z1, w2h, w2l, fc2_b, t512, BSZ, FLATD, FC1N, nbn2);
    fc3_softmax_kernel<<<BSZ, 256>>>(t512, fc3_w, fc3_b, (float*)d_out);
}

// round 17
// speedup vs baseline: 1.1726x; 1.0163x over previous
#include <cuda_runtime.h>
#include <cuda_fp16.h>
#include <math.h>
#include <stdint.h>

#define BSZ   4096
#define SEQ   36
#define DM    128
#define DFFN  512
#define NLAYER 8
#define FLATD (SEQ*DM)      // 4608
#define FC1N  13824

// ---------------- static scratch ----------------
__device__ float g_h  [(size_t)BSZ*FLATD];
__device__ float g_s  [(size_t)BSZ*FLATD];
__device__ float g_t512[(size_t)BSZ*SEQ*DFFN];   // QKV block [BL][384] / FFN scratch / z2
__device__ float g_wvo[(size_t)NLAYER*DM*DM];
__device__ float g_bvo[(size_t)NLAYER*DM];
__device__ __half g_hln[(size_t)BSZ*FLATD];      // ln output, fp16 hi plane
__device__ __half g_z1h[(size_t)BSZ*FC1N];       // fc1 output, fp16 hi plane
// fp16 hi/lo transposed weight planes [N][K]
__device__ __half g_w1h[(size_t)FC1N*FLATD];
__device__ __half g_w1l[(size_t)FC1N*FLATD];
__device__ __half g_w2h[(size_t)FLATD*FC1N];
__device__ __half g_w2l[(size_t)FLATD*FC1N];
// encoder weight planes: q,k,vo per layer [384][128] packed; conv1; conv2
__device__ __half g_eqh[(size_t)NLAYER*3*DM*DM];
__device__ __half g_eql[(size_t)NLAYER*3*DM*DM];
__device__ __half g_c1h[(size_t)NLAYER*DFFN*DM];
__device__ __half g_c1l[(size_t)NLAYER*DFFN*DM];
__device__ __half g_c2h[(size_t)NLAYER*DM*DFFN];
__device__ __half g_c2l[(size_t)NLAYER*DM*DFFN];
__device__ float  g_bqkv[(size_t)NLAYER*384];

// ============================================================================
// fp32 SGEMM — embed only (K=36)
// ============================================================================
#define BM 128
#define BN 128
#define BK 16
#define PADA 17

template<int DO_GELU, int HAS_BIAS>
__global__ __launch_bounds__(256, 2)
void sgemm_kernel(const float* __restrict__ A, const float* __restrict__ W,
                  const float* __restrict__ bias, float* __restrict__ C,
                  int M, int N, int K)
{
    __shared__ float As[BM][PADA];
    __shared__ float Ws[BK][BN];

    const int tid = threadIdx.x;
    const int tx  = tid & 15;
    const int ty  = tid >> 4;
    const size_t bm = blockIdx.y;
    const size_t bn = blockIdx.x;

    const float* Ab = A + bm * BM * (size_t)K;
    const float* Wb = W + bn * BN;

    float acc[8][8];
    #pragma unroll
    for (int i = 0; i < 8; i++)
        #pragma unroll
        for (int j = 0; j < 8; j++) acc[i][j] = 0.f;

    const int ka = tid & 15;
    const int ma = tid >> 4;
    const int nw = tid & 127;
    const int kw = tid >> 7;

    for (int k0 = 0; k0 < K; k0 += BK) {
        const bool kaok = (k0 + ka) < K;
        #pragma unroll
        for (int i = 0; i < 8; i++) {
            int m = ma + i * 16;
            float val = 0.f;
            if (kaok) val = Ab[(size_t)m * K + k0 + ka];
            As[m][ka] = val;
        }
        #pragma unroll
        for (int i = 0; i < 8; i++) {
            int kk = kw + i * 2;
            float val = 0.f;
            if (k0 + kk < K) val = Wb[(size_t)(k0 + kk) * N + nw];
            Ws[kk][nw] = val;
        }
        __syncthreads();

        #pragma unroll
        for (int kk = 0; kk < BK; kk++) {
            float ar[8];
            #pragma unroll
            for (int i = 0; i < 8; i++) ar[i] = As[ty * 8 + i][kk];
            float4 b0 = *(const float4*)&Ws[kk][tx * 8];
            float4 b1 = *(const float4*)&Ws[kk][tx * 8 + 4];
            float br[8] = {b0.x, b0.y, b0.z, b0.w, b1.x, b1.y, b1.z, b1.w};
            #pragma unroll
            for (int i = 0; i < 8; i++)
                #pragma unroll
                for (int j = 0; j < 8; j++)
                    acc[i][j] += ar[i] * br[j];
        }
        __syncthreads();
    }

    float bv[8];
    #pragma unroll
    for (int j = 0; j < 8; j++) bv[j] = 0.f;
    if (HAS_BIAS) {
        #pragma unroll
        for (int j = 0; j < 8; j++) bv[j] = bias[bn * BN + tx * 8 + j];
    }

    #pragma unroll
    for (int i = 0; i < 8; i++) {
        size_t row = bm * BM + ty * 8 + i;
        float* Cp = C + row * (size_t)N + bn * BN + tx * 8;
        float o[8];
        #pragma unroll
        for (int j = 0; j < 8; j++) {
            float vv = acc[i][j] + bv[j];
            if (DO_GELU) vv = 0.5f * vv * (1.f + erff(vv * 0.70710678118654752f));
            o[j] = vv;
        }
        *(float4*)Cp       = make_float4(o[0], o[1], o[2], o[3]);
        *(float4*)(Cp + 4) = make_float4(o[4], o[5], o[6], o[7]);
    }
}

// ============================================================================
// batched Wvo = Wv @ Wo (fp32 exact)
// ============================================================================
__global__ __launch_bounds__(256, 2)
void wvo_gemm_kernel(const float* __restrict__ Wv, const float* __restrict__ Wo,
                     float* __restrict__ Cout)
{
    __shared__ float As[BM][PADA];
    __shared__ float Ws[BK][BN];

    const int tid = threadIdx.x;
    const int tx  = tid & 15;
    const int ty  = tid >> 4;
    const size_t lay = blockIdx.x;
    const float* Ab = Wv + lay * DM * DM;
    const float* Wb = Wo + lay * DM * DM;
    float* C = Cout + lay * DM * DM;

    float acc[8][8];
    #pragma unroll
    for (int i = 0; i < 8; i++)
        #pragma unroll
        for (int j = 0; j < 8; j++) acc[i][j] = 0.f;

    const int ka = tid & 15;
    const int ma = tid >> 4;
    const int nw = tid & 127;
    const int kw = tid >> 7;

    for (int k0 = 0; k0 < DM; k0 += BK) {
        #pragma unroll
        for (int i = 0; i < 8; i++) {
            int m = ma + i * 16;
            As[m][ka] = Ab[(size_t)m * DM + k0 + ka];
        }
        #pragma unroll
        for (int i = 0; i < 8; i++) {
            int kk = kw + i * 2;
            Ws[kk][nw] = Wb[(size_t)(k0 + kk) * DM + nw];
        }
        __syncthreads();

        #pragma unroll
        for (int kk = 0; kk < BK; kk++) {
            float ar[8];
            #pragma unroll
            for (int i = 0; i < 8; i++) ar[i] = As[ty * 8 + i][kk];
            float4 b0 = *(const float4*)&Ws[kk][tx * 8];
            float4 b1 = *(const float4*)&Ws[kk][tx * 8 + 4];
            float br[8] = {b0.x, b0.y, b0.z, b0.w, b1.x, b1.y, b1.z, b1.w};
            #pragma unroll
            for (int i = 0; i < 8; i++)
                #pragma unroll
                for (int j = 0; j < 8; j++)
                    acc[i][j] += ar[i] * br[j];
        }
        __syncthreads();
    }

    #pragma unroll
    for (int i = 0; i < 8; i++) {
        size_t row = ty * 8 + i;
        float* Cp = C + row * DM + tx * 8;
        *(float4*)Cp       = make_float4(acc[i][0], acc[i][1], acc[i][2], acc[i][3]);
        *(float4*)(Cp + 4) = make_float4(acc[i][4], acc[i][5], acc[i][6], acc[i][7]);
    }
}

// ============================================================================
// prep kernels (layer-batched)
// ============================================================================
__global__ __launch_bounds__(256)
void tsplit_kernel(const float* __restrict__ src, __half* __restrict__ dh,
                   __half* __restrict__ dl, int K, int N,
                   size_t srcStride, size_t dstStride)
{
    __shared__ float t[32][33];
    const size_t z = blockIdx.z;
    const float* s = src + z * srcStride;
    __half* dhh = dh + z * dstStride;
    __half* dll = dl + z * dstStride;
    const int n0 = blockIdx.x * 32, k0 = blockIdx.y * 32;
    const int tx = threadIdx.x, ty = threadIdx.y;   // 32 x 8
    #pragma unroll
    for (int j = 0; j < 32; j += 8)
        t[ty + j][tx] = s[(size_t)(k0 + ty + j) * N + n0 + tx];
    __syncthreads();
    #pragma unroll
    for (int j = 0; j < 32; j += 8) {
        float v = t[tx][ty + j];
        __half h = __float2half_rn(v);
        const size_t o = (size_t)(n0 + ty + j) * K + k0 + tx;
        dhh[o] = h;
        dll[o] = __float2half_rn(v - __half2float(h));
    }
}

__global__ __launch_bounds__(128)
void bvo_kernel(const float* __restrict__ bv, const float* __restrict__ Wo,
                const float* __restrict__ bo, float* __restrict__ bvo)
{
    const int i = blockIdx.x;
    const int j = threadIdx.x;
    __shared__ float bs[DM];
    if (j < DM) bs[j] = bv[i * DM + j];
    __syncthreads();
    const float* wop = Wo + (size_t)i * DM * DM + j;
    float s = 0.f;
    #pragma unroll 8
    for (int k = 0; k < DM; k++) s += bs[k] * wop[(size_t)k * DM];
    bvo[i * DM + j] = s + bo[i * DM + j];
}

__global__ __launch_bounds__(384)
void packb_kernel(const float* __restrict__ bq, const float* __restrict__ bk,
                  const float* __restrict__ bvo, float* __restrict__ dst)
{
    const int i = blockIdx.x;
    const int t = threadIdx.x;
    float v = (t < 128) ? bq[i * 128 + t]
            : (t < 256) ? bk[i * 128 + t - 128]
                        : bvo[i * 128 + t - 256];
    dst[i * 384 + t] = v;
}

// ============================================================================
// common GEMM helpers
// ============================================================================
#define USTR  20
#define PLANE (128*USTR)

__device__ __forceinline__ uint32_t packh(__half a, __half b) {
    __half2 t = __halves2half2(a, b);
    return *reinterpret_cast<uint32_t*>(&t);
}
__device__ __forceinline__ uint32_t smem_u32p(const void* p) {
    uint32_t a;
    asm("{ .reg .u64 t; cvta.to.shared.u64 t, %1; cvt.u32.u64 %0, t; }" : "=r"(a) : "l"(p));
    return a;
}
__device__ __forceinline__ void cp16(uint32_t dst, const void* src) {
    asm volatile("cp.async.cg.shared.global [%0], [%1], 16;" :: "r"(dst), "l"(src) : "memory");
}

#define LDSM4(R0, R1, R2, R3, ADDR)                                              \
    asm volatile("ldmatrix.sync.aligned.m8n8.x4.shared.b16 {%0,%1,%2,%3}, [%4];" \
        : "=r"(R0), "=r"(R1), "=r"(R2), "=r"(R3) : "r"(ADDR))

#define MMA_F16(ACC, A0, A1, A2, A3, B0, B1)                                    \
    asm volatile(                                                                \
        "mma.sync.aligned.m16n8k16.row.col.f32.f16.f16.f32 "                    \
        "{%0,%1,%2,%3}, {%4,%5,%6,%7}, {%8,%9}, {%0,%1,%2,%3};\n"               \
        : "+f"(ACC[0]), "+f"(ACC[1]), "+f"(ACC[2]), "+f"(ACC[3])                \
        : "r"(A0), "r"(A1), "r"(A2), "r"(A3), "r"(B0), "r"(B1))

// ============================================================================
// 3xFP16 tensor-core GEMM (encoder; fp32 A split in loader; 4 planes)
// ============================================================================
#define STAGE (4*PLANE)
#define HSM   (2*STAGE*4)

template<int DO_GELU, int HAS_BIAS>
__global__ __launch_bounds__(256, 2)
void hgemm3_kernel(const float* __restrict__ A, const __half* __restrict__ Wh,
                   const __half* __restrict__ Wl, const float* __restrict__ bias,
                   float* __restrict__ C, int M, int N, int K, int nbn)
{
    extern __shared__ uint32_t smem[];

    const int tid  = threadIdx.x;
    const int warp = tid >> 5;
    const int lane = tid & 31;
    const int wm = warp >> 2;
    const int wn = warp & 3;
    const int g  = lane >> 2;
    const int t4 = lane & 3;

    const int per = 8 * nbn;
    const int bm = (blockIdx.x / per) * 8 + (blockIdx.x % per) % 8;
    const int bn = (blockIdx.x % per) / 8;
    const size_t bm0 = (size_t)bm * 128;
    const int bn0 = bn * 128;

    const int lrow = tid >> 1;
    const int o0   = (tid & 1) * 8;
    const int khal = o0 * 2;
    const float*  ap  = A  + (bm0 + lrow) * (size_t)K + khal;
    const __half* bph = Wh + (size_t)(bn0 + lrow) * K + khal;
    const __half* bpl = Wl + (size_t)(bn0 + lrow) * K + khal;

    const uint32_t smb = smem_u32p(smem);
    const int boff = lrow * USTR + o0;

    const int l15 = lane & 15;
    const uint32_t a_base = ((uint32_t)(wm * 64 + l15) * USTR + (lane >> 4) * 4) * 4;
    const int bl7 = (lane & 7) + ((lane >> 4) << 3);
    const uint32_t b_base = ((uint32_t)(wn * 32 + bl7) * USTR + ((lane >> 3) & 1) * 4) * 4;

    float acc[4][4][4];
    #pragma unroll
    for (int mi = 0; mi < 4; mi++)
        #pragma unroll
        for (int ni = 0; ni < 4; ni++)
            #pragma unroll
            for (int r = 0; r < 4; r++) acc[mi][ni][r] = 0.f;

    // prologue
    {
        const uint32_t dBh = smb + (2 * PLANE + boff) * 4;
        const uint32_t dBl = smb + (3 * PLANE + boff) * 4;
        cp16(dBh,      bph);     cp16(dBh + 16, bph + 8);
        cp16(dBl,      bpl);     cp16(dBl + 16, bpl + 8);
        asm volatile("cp.async.commit_group;" ::: "memory");

        float4 pa0 = *(const float4*)(ap);
        float4 pa1 = *(const float4*)(ap + 4);
        float4 pa2 = *(const float4*)(ap + 8);
        float4 pa3 = *(const float4*)(ap + 12);
        float fv[16] = {pa0.x, pa0.y, pa0.z, pa0.w, pa1.x, pa1.y, pa1.z, pa1.w,
                        pa2.x, pa2.y, pa2.z, pa2.w, pa3.x, pa3.y, pa3.z, pa3.w};
        uint32_t uh[8], ul[8];
        #pragma unroll
        for (int j = 0; j < 8; j++) {
            float a0 = fv[2 * j], a1 = fv[2 * j + 1];
            __half h0 = __float2half_rn(a0), h1 = __float2half_rn(a1);
            uh[j] = packh(h0, h1);
            ul[j] = packh(__float2half_rn(a0 - __half2float(h0)),
                          __float2half_rn(a1 - __half2float(h1)));
        }
        *(uint4*)&smem[boff]             = make_uint4(uh[0], uh[1], uh[2], uh[3]);
        *(uint4*)&smem[boff + 4]         = make_uint4(uh[4], uh[5], uh[6], uh[7]);
        *(uint4*)&smem[PLANE + boff]     = make_uint4(ul[0], ul[1], ul[2], ul[3]);
        *(uint4*)&smem[PLANE + boff + 4] = make_uint4(ul[4], ul[5], ul[6], ul[7]);
        asm volatile("cp.async.wait_group 0;" ::: "memory");
    }
    __syncthreads();

    float4 pa0, pa1, pa2, pa3;
    int it = 0;
    for (int k0 = 0; k0 < K; k0 += 32, it++) {
        const int cur = it & 1;
        const int nxt = cur ^ 1;
        const bool more = (k0 + 32) < K;

        if (more) {
            const int kn = k0 + 32;
            const uint32_t dBh = smb + (nxt * STAGE + 2 * PLANE + boff) * 4;
            const uint32_t dBl = smb + (nxt * STAGE + 3 * PLANE + boff) * 4;
            cp16(dBh,      bph + kn);     cp16(dBh + 16, bph + kn + 8);
            cp16(dBl,      bpl + kn);     cp16(dBl + 16, bpl + kn + 8);
            asm volatile("cp.async.commit_group;" ::: "memory");
            pa0 = *(const float4*)(ap + kn);
            pa1 = *(const float4*)(ap + kn + 4);
            pa2 = *(const float4*)(ap + kn + 8);
            pa3 = *(const float4*)(ap + kn + 12);
        }

        const uint32_t stb = smb + cur * STAGE * 4;
        #pragma unroll
        for (int ks = 0; ks < 2; ks++) {
            const uint32_t kbb = ks * 32;
            uint32_t af[4][4], al_[4][4], bf[4][2], bt[4][2];
            #pragma unroll
            for (int mi = 0; mi < 4; mi++) {
                const uint32_t ao = stb + a_base + (uint32_t)(mi * 16 * USTR) * 4 + kbb;
                LDSM4(af[mi][0], af[mi][1], af[mi][2], af[mi][3], ao);
                LDSM4(al_[mi][0], al_[mi][1], al_[mi][2], al_[mi][3], ao + PLANE * 4);
            }
            {
                const uint32_t bo0 = stb + (2 * PLANE) * 4 + b_base + kbb;
                const uint32_t bo1 = bo0 + (uint32_t)(16 * USTR) * 4;
                LDSM4(bf[0][0], bf[0][1], bf[1][0], bf[1][1], bo0);
                LDSM4(bf[2][0], bf[2][1], bf[3][0], bf[3][1], bo1);
                LDSM4(bt[0][0], bt[0][1], bt[1][0], bt[1][1], bo0 + PLANE * 4);
                LDSM4(bt[2][0], bt[2][1], bt[3][0], bt[3][1], bo1 + PLANE * 4);
            }
            #pragma unroll
            for (int mi = 0; mi < 4; mi++)
                #pragma unroll
                for (int ni = 0; ni < 4; ni++)
                    MMA_F16(acc[mi][ni], af[mi][0], af[mi][1], af[mi][2], af[mi][3],
                            bf[ni][0], bf[ni][1]);
            #pragma unroll
            for (int mi = 0; mi < 4; mi++)
                #pragma unroll
                for (int ni = 0; ni < 4; ni++)
                    MMA_F16(acc[mi][ni], af[mi][0], af[mi][1], af[mi][2], af[mi][3],
                            bt[ni][0], bt[ni][1]);
            #pragma unroll
            for (int mi = 0; mi < 4; mi++)
                #pragma unroll
                for (int ni = 0; ni < 4; ni++)
                    MMA_F16(acc[mi][ni], al_[mi][0], al_[mi][1], al_[mi][2], al_[mi][3],
                            bf[ni][0], bf[ni][1]);
        }

        if (more) {
            float fv[16] = {pa0.x, pa0.y, pa0.z, pa0.w, pa1.x, pa1.y, pa1.z, pa1.w,
                            pa2.x, pa2.y, pa2.z, pa2.w, pa3.x, pa3.y, pa3.z, pa3.w};
            uint32_t uh[8], ul[8];
            #pragma unroll
            for (int j = 0; j < 8; j++) {
                float a0 = fv[2 * j], a1 = fv[2 * j + 1];
                __half h0 = __float2half_rn(a0), h1 = __float2half_rn(a1);
                uh[j] = packh(h0, h1);
                ul[j] = packh(__float2half_rn(a0 - __half2float(h0)),
                              __float2half_rn(a1 - __half2float(h1)));
            }
            uint32_t* sb = smem + nxt * STAGE;
            *(uint4*)&sb[boff]             = make_uint4(uh[0], uh[1], uh[2], uh[3]);
            *(uint4*)&sb[boff + 4]         = make_uint4(uh[4], uh[5], uh[6], uh[7]);
            *(uint4*)&sb[PLANE + boff]     = make_uint4(ul[0], ul[1], ul[2], ul[3]);
            *(uint4*)&sb[PLANE + boff + 4] = make_uint4(ul[4], ul[5], ul[6], ul[7]);
            asm volatile("cp.async.wait_group 0;" ::: "memory");
        }
        __syncthreads();
    }

    #pragma unroll
    for (int ni = 0; ni < 4; ni++) {
        const int col = bn0 + wn * 32 + ni * 8 + 2 * t4;
        float b0 = 0.f, b1 = 0.f;
        if (HAS_BIAS) { b0 = bias[col]; b1 = bias[col + 1]; }
        #pragma unroll
        for (int mi = 0; mi < 4; mi++) {
            #pragma unroll
            for (int hh = 0; hh < 2; hh++) {
                const size_t row = bm0 + wm * 64 + mi * 16 + g + hh * 8;
                float v0 = acc[mi][ni][2 * hh]     + b0;
                float v1 = acc[mi][ni][2 * hh + 1] + b1;
                if (DO_GELU) {
                    v0 = 0.5f * v0 * (1.f + erff(v0 * 0.70710678118654752f));
                    v1 = 0.5f * v1 * (1.f + erff(v1 * 0.70710678118654752f));
                }
                *(float2*)(C + row * (size_t)N + col) = make_float2(v0, v1);
            }
        }
    }
}

// ============================================================================
// 2-pass head GEMM: A = pre-split fp16 hi plane; pure cp.async loader; 3 planes.
// acc = Ah*Bh + Ah*Bl = fp16(A) x exact B. Bit-identical to R16's TWO_PASS.
// OUTH=1: gelu -> fp16 hi-plane out.  OUTH=0: bias -> fp32 out.
// ============================================================================
#define STAGE2 (3*PLANE)
#define HSM2   (2*STAGE2*4)

template<int OUTH>
__global__ __launch_bounds__(256, 2)
void hgemm2h_kernel(const __half* __restrict__ Ah, const __half* __restrict__ Wh,
                    const __half* __restrict__ Wl, const float* __restrict__ bias,
                    float* __restrict__ C, __half* __restrict__ Ch,
                    int M, int N, int K, int nbn)
{
    extern __shared__ uint32_t smem[];

    const int tid  = threadIdx.x;
    const int warp = tid >> 5;
    const int lane = tid & 31;
    const int wm = warp >> 2;
    const int wn = warp & 3;
    const int g  = lane >> 2;
    const int t4 = lane & 3;

    const int per = 8 * nbn;
    const int bm = (blockIdx.x / per) * 8 + (blockIdx.x % per) % 8;
    const int bn = (blockIdx.x % per) / 8;
    const size_t bm0 = (size_t)bm * 128;
    const int bn0 = bn * 128;

    const int lrow = tid >> 1;
    const int o0   = (tid & 1) * 8;
    const int khal = o0 * 2;
    const __half* aph = Ah + (bm0 + lrow) * (size_t)K + khal;
    const __half* bph = Wh + (size_t)(bn0 + lrow) * K + khal;
    const __half* bpl = Wl + (size_t)(bn0 + lrow) * K + khal;

    const uint32_t smb = smem_u32p(smem);
    const uint32_t bo4 = (uint32_t)(lrow * USTR + o0) * 4;

    const int l15 = lane & 15;
    const uint32_t a_base = ((uint32_t)(wm * 64 + l15) * USTR + (lane >> 4) * 4) * 4;
    const int bl7 = (lane & 7) + ((lane >> 4) << 3);
    const uint32_t b_base = ((uint32_t)(wn * 32 + bl7) * USTR + ((lane >> 3) & 1) * 4) * 4;

    float acc[4][4][4];
    #pragma unroll
    for (int mi = 0; mi < 4; mi++)
        #pragma unroll
        for (int ni = 0; ni < 4; ni++)
            #pragma unroll
            for (int r = 0; r < 4; r++) acc[mi][ni][r] = 0.f;

    auto issue = [&](int stg, int kk) {
        const uint32_t sb = smb + (uint32_t)stg * STAGE2 * 4;
        cp16(sb + bo4,                       aph + kk);
        cp16(sb + bo4 + 16,                  aph + kk + 8);
        cp16(sb + PLANE * 4 + bo4,           bph + kk);
        cp16(sb + PLANE * 4 + bo4 + 16,      bph + kk + 8);
        cp16(sb + 2 * PLANE * 4 + bo4,       bpl + kk);
        cp16(sb + 2 * PLANE * 4 + bo4 + 16,  bpl + kk + 8);
        asm volatile("cp.async.commit_group;" ::: "memory");
    };

    issue(0, 0);
    asm volatile("cp.async.wait_group 0;" ::: "memory");
    __syncthreads();

    int it = 0;
    for (int k0 = 0; k0 < K; k0 += 32, it++) {
        const int cur = it & 1;
        const bool more = (k0 + 32) < K;
        if (more) issue(cur ^ 1, k0 + 32);

        const uint32_t stb = smb + (uint32_t)cur * STAGE2 * 4;
        #pragma unroll
        for (int ks = 0; ks < 2; ks++) {
            const uint32_t kbb = ks * 32;
            uint32_t af[4][4], bf[4][2], bt[4][2];
            #pragma unroll
            for (int mi = 0; mi < 4; mi++) {
                const uint32_t ao = stb + a_base + (uint32_t)(mi * 16 * USTR) * 4 + kbb;
                LDSM4(af[mi][0], af[mi][1], af[mi][2], af[mi][3], ao);
            }
            {
                const uint32_t bo0 = stb + PLANE * 4 + b_base + kbb;
                const uint32_t bo1 = bo0 + (uint32_t)(16 * USTR) * 4;
                LDSM4(bf[0][0], bf[0][1], bf[1][0], bf[1][1], bo0);
                LDSM4(bf[2][0], bf[2][1], bf[3][0], bf[3][1], bo1);
                LDSM4(bt[0][0], bt[0][1], bt[1][0], bt[1][1], bo0 + PLANE * 4);
                LDSM4(bt[2][0], bt[2][1], bt[3][0], bt[3][1], bo1 + PLANE * 4);
            }
            #pragma unroll
            for (int mi = 0; mi < 4; mi++)
                #pragma unroll
                for (int ni = 0; ni < 4; ni++)
                    MMA_F16(acc[mi][ni], af[mi][0], af[mi][1], af[mi][2], af[mi][3],
                            bf[ni][0], bf[ni][1]);
            #pragma unroll
            for (int mi = 0; mi < 4; mi++)
                #pragma unroll
                for (int ni = 0; ni < 4; ni++)
                    MMA_F16(acc[mi][ni], af[mi][0], af[mi][1], af[mi][2], af[mi][3],
                            bt[ni][0], bt[ni][1]);
        }

        if (more) asm volatile("cp.async.wait_group 0;" ::: "memory");
        __syncthreads();
    }

    #pragma unroll
    for (int ni = 0; ni < 4; ni++) {
        const int col = bn0 + wn * 32 + ni * 8 + 2 * t4;
        const float b0 = bias[col];
        const float b1 = bias[col + 1];
        #pragma unroll
        for (int mi = 0; mi < 4; mi++) {
            #pragma unroll
            for (int hh = 0; hh < 2; hh++) {
                const size_t row = bm0 + wm * 64 + mi * 16 + g + hh * 8;
                float v0 = acc[mi][ni][2 * hh]     + b0;
                float v1 = acc[mi][ni][2 * hh + 1] + b1;
                const size_t base = row * (size_t)N + col;
                if (OUTH) {
                    v0 = 0.5f * v0 * (1.f + erff(v0 * 0.70710678118654752f));
                    v1 = 0.5f * v1 * (1.f + erff(v1 * 0.70710678118654752f));
                    *(__half2*)(Ch + base) =
                        __halves2half2(__float2half_rn(v0), __float2half_rn(v1));
                } else {
                    *(float2*)(C + base) = make_float2(v0, v1);
                }
            }
        }
    }
}

// ============================================================================
// AutoCorrelation + fused series_decomp residual (reads QKV [BL][384])
// ============================================================================
__global__ __launch_bounds__(128)
void autocorr_decomp_kernel(const float* __restrict__ QKV, float* __restrict__ H)
{
    const int b = blockIdx.x;
    const int c = threadIdx.x;
    const size_t qbase = (size_t)b * SEQ * 384 + c;
    const size_t obase = (size_t)b * FLATD + c;

    float qr[SEQ], kr[SEQ];
    #pragma unroll
    for (int t = 0; t < SEQ; t++) {
        qr[t] = QKV[qbase + (size_t)t * 384];
        kr[t] = QKV[qbase + (size_t)t * 384 + 128];
    }

    float acc[SEQ];
    #pragma unroll
    for (int tau = 0; tau < SEQ; tau++) {
        float s = 0.f;
        #pragma unroll
        for (int t = 0; t < SEQ; t++) s += qr[t] * kr[(t + SEQ - tau) % SEQ];
        acc[tau] = s;
    }

    const int lane = c & 31, wid = c >> 5;
    __shared__ float red[SEQ][4];
    #pragma unroll
    for (int tau = 0; tau < SEQ; tau++) {
        float s = acc[tau];
        s += __shfl_down_sync(0xffffffffu, s, 16);
        s += __shfl_down_sync(0xffffffffu, s, 8);
        s += __shfl_down_sync(0xffffffffu, s, 4);
        s += __shfl_down_sync(0xffffffffu, s, 2);
        s += __shfl_down_sync(0xffffffffu, s, 1);
        if (lane == 0) red[tau][wid] = s;
    }
    __syncthreads();

    __shared__ float corr[SEQ];
    if (c < SEQ) corr[c] = (red[c][0] + red[c][1] + red[c][2] + red[c][3]) * (1.f / 128.f);
    __syncthreads();

    __shared__ float wsm[3];
    __shared__ int   dsm[3];
    if (c == 0) {
        float tmp[SEQ];
        for (int t = 0; t < SEQ; t++) tmp[t] = corr[t];
        float wv[3]; int dv[3];
        for (int r = 0; r < 3; r++) {
            float best = tmp[0]; int bi = 0;
            for (int t = 1; t < SEQ; t++)
                if (tmp[t] > best) { best = tmp[t]; bi = t; }
            wv[r] = best; dv[r] = bi;
            tmp[bi] = -1e30f;
        }
        float m = wv[0];
        float e0 = expf(wv[0] - m), e1 = expf(wv[1] - m), e2 = expf(wv[2] - m);
        float inv = 1.f / (e0 + e1 + e2);
        wsm[0] = e0 * inv; wsm[1] = e1 * inv; wsm[2] = e2 * inv;
        dsm[0] = dv[0]; dsm[1] = dv[1]; dsm[2] = dv[2];
    }
    __syncthreads();

    const float w0 = wsm[0], w1 = wsm[1], w2 = wsm[2];
    const int   d0 = dsm[0], d1 = dsm[1], d2 = dsm[2];
    const float* vb = QKV + qbase + 256;

    float p[SEQ];
    #pragma unroll
    for (int t = 0; t < SEQ; t++) {
        int j0 = t + d0; if (j0 >= SEQ) j0 -= SEQ;
        int j1 = t + d1; if (j1 >= SEQ) j1 -= SEQ;
        int j2 = t + d2; if (j2 >= SEQ) j2 -= SEQ;
        float a = w0 * vb[(size_t)j0 * 384] + w1 * vb[(size_t)j1 * 384]
                + w2 * vb[(size_t)j2 * 384];
        p[t] = H[obase + (size_t)t * DM] + a;
    }

    float run = 12.f * p[0];
    #pragma unroll
    for (int j = 0; j <= 12; j++) run += p[j];
    #pragma unroll
    for (int t = 0; t < SEQ; t++) {
        H[obase + (size_t)t * DM] = p[t] - run * (1.f / 25.f);
        int jn = t + 13; if (jn > SEQ - 1) jn = SEQ - 1;
        int jo = t - 12; if (jo < 0) jo = 0;
        run += p[jn] - p[jo];
    }
}

// ---------------- series_decomp with fused residual add (FFN branch) ----------------
__global__ __launch_bounds__(128)
void decomp_add_kernel(const float* __restrict__ hin, const float* __restrict__ sin_,
                       float* __restrict__ hout)
{
    const int b = blockIdx.x;
    const int c = threadIdx.x;
    __shared__ float p[SEQ][DM];
    const size_t base = (size_t)b * FLATD + c;
    #pragma unroll
    for (int t = 0; t < SEQ; t++)
        p[t][c] = hin[base + t * DM] + sin_[base + t * DM];
    __syncthreads();

    float run = 12.f * p[0][c];
    #pragma unroll
    for (int j = 0; j <= 12; j++) run += p[j][c];
    #pragma unroll
    for (int t = 0; t < SEQ; t++) {
        hout[base + t * DM] = p[t][c] - run * (1.f / 25.f);
        int jn = t + 13; if (jn > SEQ - 1) jn = SEQ - 1;
        int jo = t - 12; if (jo < 0) jo = 0;
        run += p[jn][c] - p[jo][c];
    }
}

// ---------------- my_Layernorm; writes fp16 hi plane (feeds 2-pass fc1) -------
__global__ __launch_bounds__(128)
void ln_kernel(const float* __restrict__ hin, const float* __restrict__ lnw,
               const float* __restrict__ lnb, __half* __restrict__ hout)
{
    const int b = blockIdx.x;
    const int c = threadIdx.x;
    const int lane = c & 31, wid = c >> 5;
    __shared__ float xs[SEQ][DM];
    __shared__ float r1[4], r2[4];
    const size_t base = (size_t)b * FLATD + c;
    #pragma unroll
    for (int t = 0; t < SEQ; t++) xs[t][c] = hin[base + t * DM];
    __syncthreads();

    const float gw = lnw[c], gb = lnb[c];
    for (int t = 0; t < SEQ; t++) {
        float val = xs[t][c];
        float s = val;
        s += __shfl_down_sync(0xffffffffu, s, 16);
        s += __shfl_down_sync(0xffffffffu, s, 8);
        s += __shfl_down_sync(0xffffffffu, s, 4);
        s += __shfl_down_sync(0xffffffffu, s, 2);
        s += __shfl_down_sync(0xffffffffu, s, 1);
        if (lane == 0) r1[wid] = s;
        __syncthreads();
        float mean = (r1[0] + r1[1] + r1[2] + r1[3]) * (1.f / 128.f);
        float d = val - mean;
        float sq = d * d;
        sq += __shfl_down_sync(0xffffffffu, sq, 16);
        sq += __shfl_down_sync(0xffffffffu, sq, 8);
        sq += __shfl_down_sync(0xffffffffu, sq, 4);
        sq += __shfl_down_sync(0xffffffffu, sq, 2);
        sq += __shfl_down_sync(0xffffffffu, sq, 1);
        if (lane == 0) r2[wid] = sq;
        __syncthreads();
        float var = (r2[0] + r2[1] + r2[2] + r2[3]) * (1.f / 128.f);
        xs[t][c] = d * (1.f / sqrtf(var + 1e-5f)) * gw + gb;
    }
    float cm = 0.f;
    #pragma unroll
    for (int t = 0; t < SEQ; t++) cm += xs[t][c];
    cm *= (1.f / 36.f);
    #pragma unroll
    for (int t = 0; t < SEQ; t++)
        hout[base + t * DM] = __float2half_rn(xs[t][c] - cm);
}

// ---------------- fc3 [4608 -> 2] + softmax ----------------
__global__ __launch_bounds__(256)
void fc3_softmax_kernel(const float* __restrict__ z, const float* __restrict__ w,
                        const float* __restrict__ bias, float* __restrict__ out)
{
    const int b = blockIdx.x;
    const int tid = threadIdx.x;
    const int lane = tid & 31, wid = tid >> 5;
    const float* zb = z + (size_t)b * FLATD;
    float s0 = 0.f, s1 = 0.f;
    for (int i = tid; i < FLATD; i += 256) {
        float zi = zb[i];
        s0 += zi * w[2 * i];
        s1 += zi * w[2 * i + 1];
    }
    for (int off = 16; off; off >>= 1) {
        s0 += __shfl_down_sync(0xffffffffu, s0, off);
        s1 += __shfl_down_sync(0xffffffffu, s1, off);
    }
    __shared__ float r0[8], r1[8];
    if (lane == 0) { r0[wid] = s0; r1[wid] = s1; }
    __syncthreads();
    if (tid == 0) {
        float z0 = bias[0], z1v = bias[1];
        #pragma unroll
        for (int i = 0; i < 8; i++) { z0 += r0[i]; z1v += r1[i]; }
        float m = fmaxf(z0, z1v);
        float e0 = expf(z0 - m), e1 = expf(z1v - m);
        float inv = 1.f / (e0 + e1);
        out[2 * b]     = e0 * inv;
        out[2 * b + 1] = e1 * inv;
    }
}

// ---------------- launch ----------------
extern "C" void kernel_launch(void* const* d_in, const int* in_sizes, int n_in,
                              void* d_out, int out_size)
{
    const float* x        = (const float*)d_in[0];
    const float* linear_w = (const float*)d_in[1];
    const float* linear_b = (const float*)d_in[2];
    const float* Wq = (const float*)d_in[3];
    const float* bq = (const float*)d_in[4];
    const float* Wk = (const float*)d_in[5];
    const float* bk = (const float*)d_in[6];
    const float* Wv = (const float*)d_in[7];
    const float* bv = (const float*)d_in[8];
    const float* Wo = (const float*)d_in[9];
    const float* bo = (const float*)d_in[10];
    const float* conv1_w = (const float*)d_in[11];
    const float* conv2_w = (const float*)d_in[12];
    const float* ln_w = (const float*)d_in[13];
    const float* ln_b = (const float*)d_in[14];
    const float* fc1_w = (const float*)d_in[15];
    const float* fc1_b = (const float*)d_in[16];
    const float* fc2_w = (const float*)d_in[17];
    const float* fc2_b = (const float*)d_in[18];
    const float* fc3_w = (const float*)d_in[19];
    const float* fc3_b = (const float*)d_in[20];

    float *h, *s, *t512, *wvo, *bvo, *bqkv;
    __half *hln, *z1h, *w1h, *w1l, *w2h, *w2l, *eqh, *eql, *c1h, *c1l, *c2h, *c2l;
    cudaGetSymbolAddress((void**)&h,    g_h);
    cudaGetSymbolAddress((void**)&s,    g_s);
    cudaGetSymbolAddress((void**)&t512, g_t512);
    cudaGetSymbolAddress((void**)&wvo,  g_wvo);
    cudaGetSymbolAddress((void**)&bvo,  g_bvo);
    cudaGetSymbolAddress((void**)&bqkv, g_bqkv);
    cudaGetSymbolAddress((void**)&hln,  g_hln);
    cudaGetSymbolAddress((void**)&z1h,  g_z1h);
    cudaGetSymbolAddress((void**)&w1h,  g_w1h);
    cudaGetSymbolAddress((void**)&w1l,  g_w1l);
    cudaGetSymbolAddress((void**)&w2h,  g_w2h);
    cudaGetSymbolAddress((void**)&w2l,  g_w2l);
    cudaGetSymbolAddress((void**)&eqh,  g_eqh);
    cudaGetSymbolAddress((void**)&eql,  g_eql);
    cudaGetSymbolAddress((void**)&c1h,  g_c1h);
    cudaGetSymbolAddress((void**)&c1l,  g_c1l);
    cudaGetSymbolAddress((void**)&c2h,  g_c2h);
    cudaGetSymbolAddress((void**)&c2l,  g_c2l);

    cudaFuncSetAttribute(hgemm3_kernel<0,1>, cudaFuncAttributeMaxDynamicSharedMemorySize, HSM);
    cudaFuncSetAttribute(hgemm3_kernel<1,0>, cudaFuncAttributeMaxDynamicSharedMemorySize, HSM);
    cudaFuncSetAttribute(hgemm3_kernel<0,0>, cudaFuncAttributeMaxDynamicSharedMemorySize, HSM);
    cudaFuncSetAttribute(hgemm2h_kernel<1>, cudaFuncAttributeMaxDynamicSharedMemorySize, HSM2);
    cudaFuncSetAttribute(hgemm2h_kernel<0>, cudaFuncAttributeMaxDynamicSharedMemorySize, HSM2);

    const int BL = BSZ * SEQ;   // 147456

    // ---- prep (batched) ----
    tsplit_kernel<<<dim3(FC1N/32, FLATD/32, 1), dim3(32, 8)>>>(fc1_w, w1h, w1l, FLATD, FC1N, 0, 0);
    tsplit_kernel<<<dim3(FLATD/32, FC1N/32, 1), dim3(32, 8)>>>(fc2_w, w2h, w2l, FC1N, FLATD, 0, 0);
    wvo_gemm_kernel<<<NLAYER, 256>>>(Wv, Wo, wvo);
    bvo_kernel<<<NLAYER, 128>>>(bv, Wo, bo, bvo);
    packb_kernel<<<NLAYER, 384>>>(bq, bk, bvo, bqkv);
    tsplit_kernel<<<dim3(DM/32, DM/32, NLAYER), dim3(32, 8)>>>(Wq, eqh, eql, DM, DM,
                                                               (size_t)DM*DM, (size_t)3*DM*DM);
    tsplit_kernel<<<dim3(DM/32, DM/32, NLAYER), dim3(32, 8)>>>(Wk, eqh + DM*DM, eql + DM*DM, DM, DM,
                                                               (size_t)DM*DM, (size_t)3*DM*DM);
    tsplit_kernel<<<dim3(DM/32, DM/32, NLAYER), dim3(32, 8)>>>(wvo, eqh + 2*DM*DM, eql + 2*DM*DM, DM, DM,
                                                               (size_t)DM*DM, (size_t)3*DM*DM);
    tsplit_kernel<<<dim3(DFFN/32, DM/32, NLAYER), dim3(32, 8)>>>(conv1_w, c1h, c1l, DM, DFFN,
                                                                 (size_t)DM*DFFN, (size_t)DFFN*DM);
    tsplit_kernel<<<dim3(DM/32, DFFN/32, NLAYER), dim3(32, 8)>>>(conv2_w, c2h, c2l, DFFN, DM,
                                                                 (size_t)DFFN*DM, (size_t)DM*DFFN);

    // ---- embed (fp32: K=36) ----
    sgemm_kernel<0,1><<<dim3(FLATD/BN, BSZ/BM), 256>>>(x, linear_w, linear_b, h, BSZ, FLATD, 36);

    // ---- encoder: fused Q|K|VO GEMM -> autocorr+decomp -> FFN -> decomp ----
    for (int i = 0; i < NLAYER; i++) {
        const __half* wqkvh = eqh + (size_t)(i * 3) * DM * DM;
        const __half* wqkvl = eql + (size_t)(i * 3) * DM * DM;
        const __half* w1hp = c1h + (size_t)i * DFFN * DM;
        const __half* w1lp = c1l + (size_t)i * DFFN * DM;
        const __half* w2hp = c2h + (size_t)i * DM * DFFN;
        const __half* w2lp = c2l + (size_t)i * DM * DFFN;

        hgemm3_kernel<0,1><<<(BL/128) * 3, 256, HSM>>>(h, wqkvh, wqkvl, bqkv + i*384, t512, BL, 384, DM, 3);
        autocorr_decomp_kernel<<<BSZ, 128>>>(t512, h);

        hgemm3_kernel<1,0><<<(BL/128) * (DFFN/128), 256, HSM>>>(h, w1hp, w1lp, nullptr, t512, BL, DFFN, DM, DFFN/128);
        hgemm3_kernel<0,0><<<BL/128, 256, HSM>>>(t512, w2hp, w2lp, nullptr, s, BL, DM, DFFN, 1);
        decomp_add_kernel<<<BSZ, 128>>>(h, s, h);
    }

    ln_kernel<<<BSZ, 128>>>(h, ln_w, ln_b, hln);

    // ---- head: 2-pass GEMMs with pre-split fp16 A planes ----
    const int nbn1 = FC1N / 128;   // 108
    const int nbn2 = FLATD / 128;  // 36
    hgemm2h_kernel<1><<<(BSZ/128) * nbn1, 256, HSM2>>>(hln, w1h, w1l, fc1_b, nullptr, z1h,
                                                       BSZ, FC1N, FLATD, nbn1);
    hgemm2h_kernel<0><<<(BSZ/128) * nbn2, 256, HSM2>>>(z1h, w2h, w2l, fc2_b, t512, nullptr,
                                                       BSZ, FLATD, FC1N, nbn2);
    fc3_softmax_kernel<<<BSZ, 256>>>(t512, fc3_w, fc3_b, (float*)d_out);
}